// round 1
// baseline (speedup 1.0000x reference)
#include <cuda_runtime.h>

#define HID 64
#define INCH 128
#define NMAX 50000
#define EPS_RES 0.1f
#define BN_EPS 1e-5f

// ---------------- scratch (device globals; no allocation) ----------------
__device__ __align__(128) float g_x0 [NMAX * HID];
__device__ __align__(128) float g_h  [NMAX * HID];
__device__ __align__(128) float g_out[NMAX * HID];
__device__ __align__(128) float g_t2 [NMAX * 32];
__device__ float g_al[NMAX];
__device__ float g_ar[NMAX];
__device__ float g_dinv[NMAX];
__device__ int   g_deg[NMAX];
__device__ float g_stats[2 * HID];   // [0..63] col sums, [64..127] col sumsq
__device__ float g_scale[HID];
__device__ float g_shift[HID];

// ---------------- init: self-loop degree, stats=0, identity BN ----------------
__global__ void k_init(int n) {
    int i = blockIdx.x * blockDim.x + threadIdx.x;
    if (i < n) g_deg[i] = 1;                   // self-loop
    if (i < 2 * HID) g_stats[i] = 0.f;
    if (i < HID) { g_scale[i] = 1.f; g_shift[i] = 0.f; }
}

__global__ void k_deg(const int* __restrict__ dst, int E) {
    int e = blockIdx.x * blockDim.x + threadIdx.x;
    if (e < E) atomicAdd(&g_deg[dst[e]], 1);
}

__global__ void k_dinv(int n) {
    int i = blockIdx.x * blockDim.x + threadIdx.x;
    if (i < n) g_dinv[i] = rsqrtf((float)g_deg[i]);
}

// ---------------- x0 = relu(x @ W_in + b_in); h = x0 ----------------
__global__ void k_ingemm(const float* __restrict__ x, const float* __restrict__ W,
                         const float* __restrict__ b, int n) {
    __shared__ float Ws[INCH * HID];   // 32 KB
    __shared__ float xs[4][INCH];
    int tx = threadIdx.x, ty = threadIdx.y;
    int tid = ty * 64 + tx;
    for (int i = tid; i < INCH * HID; i += 256) Ws[i] = W[i];
    int row0 = blockIdx.x * 4;
    for (int t = tid; t < 4 * INCH; t += 256) {
        int r = t >> 7, k = t & 127;
        int gr = row0 + r;
        xs[r][k] = (gr < n) ? x[gr * INCH + k] : 0.f;
    }
    __syncthreads();
    int row = row0 + ty;
    if (row >= n) return;
    float acc = b[tx];
#pragma unroll 8
    for (int k = 0; k < INCH; k++) acc += xs[ty][k] * Ws[k * HID + tx];
    float v = fmaxf(acc, 0.f);
    g_x0[row * HID + tx] = v;
    g_h [row * HID + tx] = v;
}

// ---------------- per-node pre-pass (one warp per node) ----------------
// Applies previous layer's BN (scale/shift), writes normalized h back,
// computes al/ar attention projections, and initializes
// out = EPS*x0 + selfloop_msg  (self-loop never hits the atomic kernel).
__global__ void k_node_pre(const float* __restrict__ attl,
                           const float* __restrict__ attr, int n) {
    int gt = blockIdx.x * blockDim.x + threadIdx.x;
    int node = gt >> 5, lane = threadIdx.x & 31;
    if (node >= n) return;
    int c0 = lane * 2;
    int base = node * HID + c0;
    float2 y = *(const float2*)&g_h[base];
    float h0 = y.x * g_scale[c0]     + g_shift[c0];
    float h1 = y.y * g_scale[c0 + 1] + g_shift[c0 + 1];
    *(float2*)&g_h[base] = make_float2(h0, h1);
    float a = h0 * attl[c0] + h1 * attl[c0 + 1];
    float r = h0 * attr[c0] + h1 * attr[c0 + 1];
#pragma unroll
    for (int o = 16; o; o >>= 1) {
        a += __shfl_xor_sync(0xffffffffu, a, o);
        r += __shfl_xor_sync(0xffffffffu, r, o);
    }
    if (lane == 0) { g_al[node] = a; g_ar[node] = r; }
    float dv = g_dinv[node];
    float w = tanhf(a + r) * dv * dv;
    float2 x0v = *(const float2*)&g_x0[base];
    *(float2*)&g_out[base] =
        make_float2(EPS_RES * x0v.x + w * h0, EPS_RES * x0v.y + w * h1);
}

// ---------------- edge scatter: 16 threads per edge, vec4 reductions ----------------
__global__ void k_edges(const int* __restrict__ src, const int* __restrict__ dst, int E) {
    int idx = blockIdx.x * blockDim.x + threadIdx.x;
    int e = idx >> 4;
    if (e >= E) return;
    int q = idx & 15;
    int s = __ldg(&src[e]);
    int d = __ldg(&dst[e]);
    float w = tanhf(g_al[s] + g_ar[d]) * g_dinv[s] * g_dinv[d];
    float4 hv = *(const float4*)&g_h[s * HID + q * 4];
    float* p = &g_out[d * HID + q * 4];
    asm volatile("red.global.add.v4.f32 [%0], {%1,%2,%3,%4};"
                 :: "l"(p), "f"(hv.x * w), "f"(hv.y * w), "f"(hv.z * w), "f"(hv.w * w)
                 : "memory");
}

// ---------------- y = relu(out); h <- y; accumulate BN stats ----------------
__global__ void k_relu_stats(int n) {
    __shared__ float ssum[HID], ssq[HID];
    int tid = threadIdx.x;
    if (tid < HID) { ssum[tid] = 0.f; ssq[tid] = 0.f; }
    __syncthreads();
    int total4 = n * HID / 4;
    int start = blockIdx.x * blockDim.x + tid;
    int stride = gridDim.x * blockDim.x;       // multiple of 16 -> fixed col group
    float4 ls = make_float4(0, 0, 0, 0), lq = make_float4(0, 0, 0, 0);
    for (int i = start; i < total4; i += stride) {
        float4 v = *(const float4*)&g_out[i * 4];
        v.x = fmaxf(v.x, 0.f); v.y = fmaxf(v.y, 0.f);
        v.z = fmaxf(v.z, 0.f); v.w = fmaxf(v.w, 0.f);
        *(float4*)&g_h[i * 4] = v;
        ls.x += v.x; ls.y += v.y; ls.z += v.z; ls.w += v.w;
        lq.x += v.x * v.x; lq.y += v.y * v.y; lq.z += v.z * v.z; lq.w += v.w * v.w;
    }
    int c4 = start & 15;
    atomicAdd(&ssum[c4 * 4 + 0], ls.x); atomicAdd(&ssum[c4 * 4 + 1], ls.y);
    atomicAdd(&ssum[c4 * 4 + 2], ls.z); atomicAdd(&ssum[c4 * 4 + 3], ls.w);
    atomicAdd(&ssq[c4 * 4 + 0], lq.x);  atomicAdd(&ssq[c4 * 4 + 1], lq.y);
    atomicAdd(&ssq[c4 * 4 + 2], lq.z);  atomicAdd(&ssq[c4 * 4 + 3], lq.w);
    __syncthreads();
    if (tid < HID) {
        atomicAdd(&g_stats[tid], ssum[tid]);
        atomicAdd(&g_stats[HID + tid], ssq[tid]);
    }
}

// ---------------- BN finalize: scale/shift from stats; re-zero stats ----------------
__global__ void k_finalize(const float* __restrict__ g, const float* __restrict__ b,
                           float inv_n) {
    int c = threadIdx.x;
    float mean = g_stats[c] * inv_n;
    float var = g_stats[HID + c] * inv_n - mean * mean;
    float sc = g[c] * rsqrtf(var + BN_EPS);
    g_scale[c] = sc;
    g_shift[c] = b[c] - mean * sc;
    g_stats[c] = 0.f;
    g_stats[HID + c] = 0.f;
}

// ---------------- head: t1 = bn2(h)[:bs] @ W1 + b1 ; stats ----------------
__global__ void k_head1(const float* __restrict__ W1, const float* __restrict__ b1, int bs) {
    __shared__ float Ws[HID * HID];
    __shared__ float hs[4][HID];
    __shared__ float ssum[HID], ssq[HID];
    int tx = threadIdx.x, ty = threadIdx.y;
    int tid = ty * 64 + tx;
    for (int i = tid; i < HID * HID; i += 256) Ws[i] = W1[i];
    int row = blockIdx.x * 4 + ty;
    hs[ty][tx] = (row < bs) ? g_h[row * HID + tx] * g_scale[tx] + g_shift[tx] : 0.f;
    if (tid < HID) { ssum[tid] = 0.f; ssq[tid] = 0.f; }
    __syncthreads();
    float acc = b1[tx];
#pragma unroll
    for (int k = 0; k < HID; k++) acc += hs[ty][k] * Ws[k * HID + tx];
    if (row < bs) g_out[row * HID + tx] = acc; else acc = 0.f;
    atomicAdd(&ssum[tx], acc);
    atomicAdd(&ssq[tx], acc * acc);
    __syncthreads();
    if (tid < HID) {
        atomicAdd(&g_stats[tid], ssum[tid]);
        atomicAdd(&g_stats[HID + tid], ssq[tid]);
    }
}

// ---------------- head: t2 = relu(bn(t1)) @ W2 + b2 ; stats ----------------
__global__ void k_head2(const float* __restrict__ W2, const float* __restrict__ b2, int bs) {
    __shared__ float Ws[HID * 32];
    __shared__ float us[8][HID];
    __shared__ float ssum[32], ssq[32];
    int tx = threadIdx.x, ty = threadIdx.y;   // 32 x 8
    int tid = ty * 32 + tx;
    for (int i = tid; i < HID * 32; i += 256) Ws[i] = W2[i];
    int row = blockIdx.x * 8 + ty;
    if (row < bs) {
        float v0 = g_out[row * HID + tx]      * g_scale[tx]      + g_shift[tx];
        float v1 = g_out[row * HID + 32 + tx] * g_scale[32 + tx] + g_shift[32 + tx];
        us[ty][tx] = fmaxf(v0, 0.f);
        us[ty][32 + tx] = fmaxf(v1, 0.f);
    } else { us[ty][tx] = 0.f; us[ty][32 + tx] = 0.f; }
    if (tid < 32) { ssum[tid] = 0.f; ssq[tid] = 0.f; }
    __syncthreads();
    float acc = b2[tx];
#pragma unroll
    for (int k = 0; k < HID; k++) acc += us[ty][k] * Ws[k * 32 + tx];
    if (row < bs) g_t2[row * 32 + tx] = acc; else acc = 0.f;
    atomicAdd(&ssum[tx], acc);
    atomicAdd(&ssq[tx], acc * acc);
    __syncthreads();
    if (tid < 32) {
        atomicAdd(&g_stats[tid], ssum[tid]);
        atomicAdd(&g_stats[HID + tid], ssq[tid]);
    }
}

// ---------------- head: out = relu(bn(t2)) @ W3 + b3 ----------------
__global__ void k_head3(const float* __restrict__ W3, const float* __restrict__ b3,
                        float* __restrict__ out, int bs) {
    int gt = blockIdx.x * blockDim.x + threadIdx.x;
    int row = gt >> 5, lane = threadIdx.x & 31;
    if (row >= bs) return;
    float v = g_t2[row * 32 + lane] * g_scale[lane] + g_shift[lane];
    v = fmaxf(v, 0.f) * W3[lane];
#pragma unroll
    for (int o = 16; o; o >>= 1) v += __shfl_xor_sync(0xffffffffu, v, o);
    if (lane == 0) out[row] = v + b3[0];
}

extern "C" void kernel_launch(void* const* d_in, const int* in_sizes, int n_in,
                              void* d_out, int out_size) {
    const float* x    = (const float*)d_in[0];
    const int*   ei   = (const int*)d_in[1];
    int E = in_sizes[1] / 2;
    int n = in_sizes[0] / INCH;
    const float* W_in  = (const float*)d_in[3];
    const float* b_in  = (const float*)d_in[4];
    const float* att_l = (const float*)d_in[5];
    const float* att_r = (const float*)d_in[6];
    const float* bn_g  = (const float*)d_in[7];
    const float* bn_b  = (const float*)d_in[8];
    const float* W1  = (const float*)d_in[9];
    const float* b1  = (const float*)d_in[10];
    const float* g1  = (const float*)d_in[11];
    const float* be1 = (const float*)d_in[12];
    const float* W2  = (const float*)d_in[13];
    const float* b2  = (const float*)d_in[14];
    const float* g2  = (const float*)d_in[15];
    const float* be2 = (const float*)d_in[16];
    const float* W3  = (const float*)d_in[17];
    const float* b3  = (const float*)d_in[18];
    const int* src = ei;
    const int* dst = ei + E;
    int bs = out_size;   // output shape is (batch_size,)

    k_init<<<(n + 255) / 256, 256>>>(n);
    k_deg<<<(E + 255) / 256, 256>>>(dst, E);
    k_dinv<<<(n + 255) / 256, 256>>>(n);
    k_ingemm<<<(n + 3) / 4, dim3(64, 4)>>>(x, W_in, b_in, n);

    for (int l = 0; l < 3; l++) {
        k_node_pre<<<(n + 7) / 8, 256>>>(att_l + l * HID, att_r + l * HID, n);
        k_edges<<<(E * 16 + 255) / 256, 256>>>(src, dst, E);
        k_relu_stats<<<1024, 256>>>(n);
        k_finalize<<<1, HID>>>(bn_g + l * HID, bn_b + l * HID, 1.0f / n);
    }

    k_head1<<<(bs + 3) / 4, dim3(64, 4)>>>(W1, b1, bs);
    k_finalize<<<1, HID>>>(g1, be1, 1.0f / bs);
    k_head2<<<(bs + 7) / 8, dim3(32, 8)>>>(W2, b2, bs);
    k_finalize<<<1, 32>>>(g2, be2, 1.0f / bs);
    k_head3<<<(bs * 32 + 255) / 256, 256>>>(W3, b3, (float*)d_out, bs);
}

// round 3
// speedup vs baseline: 1.1157x; 1.1157x over previous
#include <cuda_runtime.h>

#define HID 64
#define INCH 128
#define NMAX 50000
#define EPS_RES 0.1f
#define BN_EPS 1e-5f

// ---------------- scratch (device globals; no allocation) ----------------
__device__ __align__(128) float g_x0 [NMAX * HID];
__device__ __align__(128) float g_h  [NMAX * HID];
__device__ __align__(128) float g_out[NMAX * HID];
__device__ __align__(128) float g_t2 [NMAX * 32];
__device__ float g_al[NMAX];
__device__ float g_ar[NMAX];
__device__ float g_dinv[NMAX];
__device__ int   g_deg[NMAX];
__device__ float g_stats[2 * HID];   // [0..63] col sums, [64..127] col sumsq
__device__ float g_scale[HID];
__device__ float g_shift[HID];

// ---------------- init: self-loop degree, stats=0, identity BN ----------------
__global__ void k_init(int n) {
    int i = blockIdx.x * blockDim.x + threadIdx.x;
    if (i < n) g_deg[i] = 1;                   // self-loop
    if (i < 2 * HID) g_stats[i] = 0.f;
    if (i < HID) { g_scale[i] = 1.f; g_shift[i] = 0.f; }
}

__global__ void k_deg(const int* __restrict__ dst, int E) {
    int e = blockIdx.x * blockDim.x + threadIdx.x;
    if (e < E) atomicAdd(&g_deg[dst[e]], 1);
}

__global__ void k_dinv(int n) {
    int i = blockIdx.x * blockDim.x + threadIdx.x;
    if (i < n) g_dinv[i] = rsqrtf((float)g_deg[i]);
}

// ---------------- x0 = relu(x @ W_in + b_in); h = x0 ----------------
// Register-tiled: 256 threads, block computes 64 rows x 64 cols.
// Each thread: 4 rows x 4 cols (float4 on the col axis).
// xs stride is INCH (128 floats): float4 stores stay 16B-aligned; inner-loop
// reads are warp-broadcast so no padding is needed.
__global__ __launch_bounds__(256) void k_ingemm(
        const float* __restrict__ x, const float* __restrict__ W,
        const float* __restrict__ b, int n) {
    __shared__ float Ws[INCH * HID];          // 32 KB, [k][col]
    __shared__ float xs[64][INCH];            // 32 KB
    int tid = threadIdx.x;
    int tx = tid & 15;          // col group: cols tx*4 .. tx*4+3
    int ty = tid >> 4;          // row group: rows ty*4 .. ty*4+3
    int row0 = blockIdx.x * 64;

    // load W (row-major [k][col]) via float4
    const float4* W4 = (const float4*)W;
    float4* Ws4 = (float4*)Ws;
    for (int i = tid; i < INCH * HID / 4; i += 256) Ws4[i] = W4[i];
    // load x tile: 64 rows x 128 cols
    for (int i = tid; i < 64 * 32; i += 256) {
        int r = i >> 5, c4 = (i & 31) * 4;
        int gr = row0 + r;
        float4 v = (gr < n) ? *(const float4*)&x[gr * INCH + c4]
                            : make_float4(0.f, 0.f, 0.f, 0.f);
        *(float4*)&xs[r][c4] = v;
    }
    __syncthreads();

    float acc[4][4];
#pragma unroll
    for (int i = 0; i < 4; i++)
#pragma unroll
        for (int j = 0; j < 4; j++) acc[i][j] = 0.f;

    int r0 = ty * 4, c0 = tx * 4;
#pragma unroll 4
    for (int k = 0; k < INCH; k++) {
        float4 wv = *(const float4*)&Ws[k * HID + c0];
        float a0 = xs[r0 + 0][k];
        float a1 = xs[r0 + 1][k];
        float a2 = xs[r0 + 2][k];
        float a3 = xs[r0 + 3][k];
        acc[0][0] += a0 * wv.x; acc[0][1] += a0 * wv.y; acc[0][2] += a0 * wv.z; acc[0][3] += a0 * wv.w;
        acc[1][0] += a1 * wv.x; acc[1][1] += a1 * wv.y; acc[1][2] += a1 * wv.z; acc[1][3] += a1 * wv.w;
        acc[2][0] += a2 * wv.x; acc[2][1] += a2 * wv.y; acc[2][2] += a2 * wv.z; acc[2][3] += a2 * wv.w;
        acc[3][0] += a3 * wv.x; acc[3][1] += a3 * wv.y; acc[3][2] += a3 * wv.z; acc[3][3] += a3 * wv.w;
    }

    float4 bv = *(const float4*)&b[c0];
#pragma unroll
    for (int i = 0; i < 4; i++) {
        int gr = row0 + r0 + i;
        if (gr >= n) break;
        float4 v;
        v.x = fmaxf(acc[i][0] + bv.x, 0.f);
        v.y = fmaxf(acc[i][1] + bv.y, 0.f);
        v.z = fmaxf(acc[i][2] + bv.z, 0.f);
        v.w = fmaxf(acc[i][3] + bv.w, 0.f);
        *(float4*)&g_x0[gr * HID + c0] = v;
        *(float4*)&g_h [gr * HID + c0] = v;
    }
}

// ---------------- per-node pre-pass (one warp per node) ----------------
__global__ void k_node_pre(const float* __restrict__ attl,
                           const float* __restrict__ attr, int n) {
    int gt = blockIdx.x * blockDim.x + threadIdx.x;
    int node = gt >> 5, lane = threadIdx.x & 31;
    if (node >= n) return;
    int c0 = lane * 2;
    int base = node * HID + c0;
    float2 y = *(const float2*)&g_h[base];
    float h0 = y.x * g_scale[c0]     + g_shift[c0];
    float h1 = y.y * g_scale[c0 + 1] + g_shift[c0 + 1];
    *(float2*)&g_h[base] = make_float2(h0, h1);
    float a = h0 * attl[c0] + h1 * attl[c0 + 1];
    float r = h0 * attr[c0] + h1 * attr[c0 + 1];
#pragma unroll
    for (int o = 16; o; o >>= 1) {
        a += __shfl_xor_sync(0xffffffffu, a, o);
        r += __shfl_xor_sync(0xffffffffu, r, o);
    }
    if (lane == 0) { g_al[node] = a; g_ar[node] = r; }
    float dv = g_dinv[node];
    float w = tanhf(a + r) * dv * dv;
    float2 x0v = *(const float2*)&g_x0[base];
    *(float2*)&g_out[base] =
        make_float2(EPS_RES * x0v.x + w * h0, EPS_RES * x0v.y + w * h1);
}

// ---------------- edge scatter: 16 threads/edge, leader computes weight ----------------
__global__ void k_edges(const int* __restrict__ src, const int* __restrict__ dst, int E) {
    int idx = blockIdx.x * blockDim.x + threadIdx.x;
    int e = idx >> 4;
    if (e >= E) return;
    int q = idx & 15;
    int s = 0, d = 0;
    float w = 0.f;
    if (q == 0) {
        s = __ldg(&src[e]);
        d = __ldg(&dst[e]);
        w = tanhf(g_al[s] + g_ar[d]) * g_dinv[s] * g_dinv[d];
    }
    s = __shfl_sync(0xffffffffu, s, 0, 16);
    d = __shfl_sync(0xffffffffu, d, 0, 16);
    w = __shfl_sync(0xffffffffu, w, 0, 16);
    float4 hv = *(const float4*)&g_h[s * HID + q * 4];
    float* p = &g_out[d * HID + q * 4];
    asm volatile("red.global.add.v4.f32 [%0], {%1,%2,%3,%4};"
                 :: "l"(p), "f"(hv.x * w), "f"(hv.y * w), "f"(hv.z * w), "f"(hv.w * w)
                 : "memory");
}

// ---------------- y = relu(out); h <- y; accumulate BN stats ----------------
__global__ void k_relu_stats(int n) {
    __shared__ float ssum[HID], ssq[HID];
    int tid = threadIdx.x;
    if (tid < HID) { ssum[tid] = 0.f; ssq[tid] = 0.f; }
    __syncthreads();
    int total4 = n * HID / 4;
    int start = blockIdx.x * blockDim.x + tid;
    int stride = gridDim.x * blockDim.x;       // multiple of 16 -> fixed col group
    float4 ls = make_float4(0, 0, 0, 0), lq = make_float4(0, 0, 0, 0);
    for (int i = start; i < total4; i += stride) {
        float4 v = *(const float4*)&g_out[i * 4];
        v.x = fmaxf(v.x, 0.f); v.y = fmaxf(v.y, 0.f);
        v.z = fmaxf(v.z, 0.f); v.w = fmaxf(v.w, 0.f);
        *(float4*)&g_h[i * 4] = v;
        ls.x += v.x; ls.y += v.y; ls.z += v.z; ls.w += v.w;
        lq.x += v.x * v.x; lq.y += v.y * v.y; lq.z += v.z * v.z; lq.w += v.w * v.w;
    }
    int c4 = start & 15;
    atomicAdd(&ssum[c4 * 4 + 0], ls.x); atomicAdd(&ssum[c4 * 4 + 1], ls.y);
    atomicAdd(&ssum[c4 * 4 + 2], ls.z); atomicAdd(&ssum[c4 * 4 + 3], ls.w);
    atomicAdd(&ssq[c4 * 4 + 0], lq.x);  atomicAdd(&ssq[c4 * 4 + 1], lq.y);
    atomicAdd(&ssq[c4 * 4 + 2], lq.z);  atomicAdd(&ssq[c4 * 4 + 3], lq.w);
    __syncthreads();
    if (tid < HID) {
        atomicAdd(&g_stats[tid], ssum[tid]);
        atomicAdd(&g_stats[HID + tid], ssq[tid]);
    }
}

// ---------------- BN finalize: scale/shift from stats; re-zero stats ----------------
__global__ void k_finalize(const float* __restrict__ g, const float* __restrict__ b,
                           float inv_n) {
    int c = threadIdx.x;
    float mean = g_stats[c] * inv_n;
    float var = g_stats[HID + c] * inv_n - mean * mean;
    float sc = g[c] * rsqrtf(var + BN_EPS);
    g_scale[c] = sc;
    g_shift[c] = b[c] - mean * sc;
    g_stats[c] = 0.f;
    g_stats[HID + c] = 0.f;
}

// ---------------- head: t1 = bn2(h)[:bs] @ W1 + b1 ; stats ----------------
__global__ void k_head1(const float* __restrict__ W1, const float* __restrict__ b1, int bs) {
    __shared__ float Ws[HID * HID];
    __shared__ float hs[4][HID];
    __shared__ float ssum[HID], ssq[HID];
    int tx = threadIdx.x, ty = threadIdx.y;
    int tid = ty * 64 + tx;
    for (int i = tid; i < HID * HID; i += 256) Ws[i] = W1[i];
    int row = blockIdx.x * 4 + ty;
    hs[ty][tx] = (row < bs) ? g_h[row * HID + tx] * g_scale[tx] + g_shift[tx] : 0.f;
    if (tid < HID) { ssum[tid] = 0.f; ssq[tid] = 0.f; }
    __syncthreads();
    float acc = b1[tx];
#pragma unroll
    for (int k = 0; k < HID; k++) acc += hs[ty][k] * Ws[k * HID + tx];
    if (row < bs) g_out[row * HID + tx] = acc; else acc = 0.f;
    atomicAdd(&ssum[tx], acc);
    atomicAdd(&ssq[tx], acc * acc);
    __syncthreads();
    if (tid < HID) {
        atomicAdd(&g_stats[tid], ssum[tid]);
        atomicAdd(&g_stats[HID + tid], ssq[tid]);
    }
}

// ---------------- head: t2 = relu(bn(t1)) @ W2 + b2 ; stats ----------------
__global__ void k_head2(const float* __restrict__ W2, const float* __restrict__ b2, int bs) {
    __shared__ float Ws[HID * 32];
    __shared__ float us[8][HID];
    __shared__ float ssum[32], ssq[32];
    int tx = threadIdx.x, ty = threadIdx.y;   // 32 x 8
    int tid = ty * 32 + tx;
    for (int i = tid; i < HID * 32; i += 256) Ws[i] = W2[i];
    int row = blockIdx.x * 8 + ty;
    if (row < bs) {
        float v0 = g_out[row * HID + tx]      * g_scale[tx]      + g_shift[tx];
        float v1 = g_out[row * HID + 32 + tx] * g_scale[32 + tx] + g_shift[32 + tx];
        us[ty][tx] = fmaxf(v0, 0.f);
        us[ty][32 + tx] = fmaxf(v1, 0.f);
    } else { us[ty][tx] = 0.f; us[ty][32 + tx] = 0.f; }
    if (tid < 32) { ssum[tid] = 0.f; ssq[tid] = 0.f; }
    __syncthreads();
    float acc = b2[tx];
#pragma unroll
    for (int k = 0; k < HID; k++) acc += us[ty][k] * Ws[k * 32 + tx];
    if (row < bs) g_t2[row * 32 + tx] = acc; else acc = 0.f;
    atomicAdd(&ssum[tx], acc);
    atomicAdd(&ssq[tx], acc * acc);
    __syncthreads();
    if (tid < 32) {
        atomicAdd(&g_stats[tid], ssum[tid]);
        atomicAdd(&g_stats[HID + tid], ssq[tid]);
    }
}

// ---------------- head: out = relu(bn(t2)) @ W3 + b3 ----------------
__global__ void k_head3(const float* __restrict__ W3, const float* __restrict__ b3,
                        float* __restrict__ out, int bs) {
    int gt = blockIdx.x * blockDim.x + threadIdx.x;
    int row = gt >> 5, lane = threadIdx.x & 31;
    if (row >= bs) return;
    float v = g_t2[row * 32 + lane] * g_scale[lane] + g_shift[lane];
    v = fmaxf(v, 0.f) * W3[lane];
#pragma unroll
    for (int o = 16; o; o >>= 1) v += __shfl_xor_sync(0xffffffffu, v, o);
    if (lane == 0) out[row] = v + b3[0];
}

extern "C" void kernel_launch(void* const* d_in, const int* in_sizes, int n_in,
                              void* d_out, int out_size) {
    const float* x    = (const float*)d_in[0];
    const int*   ei   = (const int*)d_in[1];
    int E = in_sizes[1] / 2;
    int n = in_sizes[0] / INCH;
    const float* W_in  = (const float*)d_in[3];
    const float* b_in  = (const float*)d_in[4];
    const float* att_l = (const float*)d_in[5];
    const float* att_r = (const float*)d_in[6];
    const float* bn_g  = (const float*)d_in[7];
    const float* bn_b  = (const float*)d_in[8];
    const float* W1  = (const float*)d_in[9];
    const float* b1  = (const float*)d_in[10];
    const float* g1  = (const float*)d_in[11];
    const float* be1 = (const float*)d_in[12];
    const float* W2  = (const float*)d_in[13];
    const float* b2  = (const float*)d_in[14];
    const float* g2  = (const float*)d_in[15];
    const float* be2 = (const float*)d_in[16];
    const float* W3  = (const float*)d_in[17];
    const float* b3  = (const float*)d_in[18];
    const int* src = ei;
    const int* dst = ei + E;
    int bs = out_size;   // output shape is (batch_size,)

    k_init<<<(n + 255) / 256, 256>>>(n);
    k_deg<<<(E + 255) / 256, 256>>>(dst, E);
    k_dinv<<<(n + 255) / 256, 256>>>(n);
    k_ingemm<<<(n + 63) / 64, 256>>>(x, W_in, b_in, n);

    for (int l = 0; l < 3; l++) {
        k_node_pre<<<(n + 7) / 8, 256>>>(att_l + l * HID, att_r + l * HID, n);
        k_edges<<<(E * 16 + 255) / 256, 256>>>(src, dst, E);
        k_relu_stats<<<1024, 256>>>(n);
        k_finalize<<<1, HID>>>(bn_g + l * HID, bn_b + l * HID, 1.0f / n);
    }

    k_head1<<<(bs + 3) / 4, dim3(64, 4)>>>(W1, b1, bs);
    k_finalize<<<1, HID>>>(g1, be1, 1.0f / bs);
    k_head2<<<(bs + 7) / 8, dim3(32, 8)>>>(W2, b2, bs);
    k_finalize<<<1, 32>>>(g2, be2, 1.0f / bs);
    k_head3<<<(bs * 32 + 255) / 256, 256>>>(W3, b3, (float*)d_out, bs);
}

// round 4
// speedup vs baseline: 1.2724x; 1.1404x over previous
#include <cuda_runtime.h>

#define HID 64
#define INCH 128
#define NMAX 50000
#define EMAX 1200000
#define EPS_RES 0.1f
#define BN_EPS 1e-5f

// ---------------- scratch (device globals; no allocation) ----------------
__device__ __align__(128) float g_x0 [NMAX * HID];
__device__ __align__(128) float g_h  [NMAX * HID];
__device__ __align__(128) float g_out[NMAX * HID];
__device__ __align__(128) float g_t2 [NMAX * 32];
__device__ float g_al[NMAX];
__device__ float g_ar[NMAX];
__device__ float g_dinv[NMAX];
__device__ int   g_deg[NMAX];
__device__ int   g_off[NMAX + 1];
__device__ int   g_cur[NMAX];
__device__ int   g_csrc[EMAX];
__device__ int   g_cdst[EMAX];
__device__ float g_w[EMAX];
__device__ float g_stats[2 * HID];   // [0..63] col sums, [64..127] col sumsq
__device__ float g_scale[HID];
__device__ float g_shift[HID];

// ---------------- init ----------------
__global__ void k_init(int n) {
    int i = blockIdx.x * blockDim.x + threadIdx.x;
    if (i < n) { g_deg[i] = 1; g_cur[i] = 0; }      // self-loop counted in deg
    if (i < 2 * HID) g_stats[i] = 0.f;
    if (i < HID) { g_scale[i] = 1.f; g_shift[i] = 0.f; }
}

__global__ void k_deg(const int* __restrict__ dst, int E) {
    int e = blockIdx.x * blockDim.x + threadIdx.x;
    if (e < E) atomicAdd(&g_deg[dst[e]], 1);
}

__global__ void k_dinv(int n) {
    int i = blockIdx.x * blockDim.x + threadIdx.x;
    if (i < n) g_dinv[i] = rsqrtf((float)g_deg[i]);
}

// ---------------- exclusive scan of (deg-1) -> CSR row offsets ----------------
__global__ __launch_bounds__(1024) void k_scan(int n) {
    __shared__ int sp[1024];
    int t = threadIdx.x;
    int chunk = (n + 1023) / 1024;
    int beg = t * chunk;
    int end = min(beg + chunk, n);
    int s = 0;
    for (int i = beg; i < end; i++) s += g_deg[i] - 1;
    sp[t] = s;
    __syncthreads();
    for (int o = 1; o < 1024; o <<= 1) {
        int v = (t >= o) ? sp[t - o] : 0;
        __syncthreads();
        sp[t] += v;
        __syncthreads();
    }
    int run = (t > 0) ? sp[t - 1] : 0;   // exclusive prefix of this chunk
    for (int i = beg; i < end; i++) { g_off[i] = run; run += g_deg[i] - 1; }
    if (t == 0) g_off[n] = sp[1023];
}

// ---------------- scatter edges into CSR (grouped by dst) ----------------
__global__ void k_scatter(const int* __restrict__ src, const int* __restrict__ dst, int E) {
    int e = blockIdx.x * blockDim.x + threadIdx.x;
    if (e >= E) return;
    int d = dst[e];
    int pos = g_off[d] + atomicAdd(&g_cur[d], 1);
    g_csrc[pos] = src[e];
    g_cdst[pos] = d;
}

// ---------------- x0 = relu(x @ W_in + b_in); also seed g_out = x0 ----------------
__global__ __launch_bounds__(256) void k_ingemm(
        const float* __restrict__ x, const float* __restrict__ W,
        const float* __restrict__ b, int n) {
    __shared__ float Ws[INCH * HID];          // 32 KB, [k][col]
    __shared__ float xs[64][INCH];            // 32 KB
    int tid = threadIdx.x;
    int tx = tid & 15;
    int ty = tid >> 4;
    int row0 = blockIdx.x * 64;

    const float4* W4 = (const float4*)W;
    float4* Ws4 = (float4*)Ws;
    for (int i = tid; i < INCH * HID / 4; i += 256) Ws4[i] = W4[i];
    for (int i = tid; i < 64 * 32; i += 256) {
        int r = i >> 5, c4 = (i & 31) * 4;
        int gr = row0 + r;
        float4 v = (gr < n) ? *(const float4*)&x[gr * INCH + c4]
                            : make_float4(0.f, 0.f, 0.f, 0.f);
        *(float4*)&xs[r][c4] = v;
    }
    __syncthreads();

    float acc[4][4];
#pragma unroll
    for (int i = 0; i < 4; i++)
#pragma unroll
        for (int j = 0; j < 4; j++) acc[i][j] = 0.f;

    int r0 = ty * 4, c0 = tx * 4;
#pragma unroll 4
    for (int k = 0; k < INCH; k++) {
        float4 wv = *(const float4*)&Ws[k * HID + c0];
        float a0 = xs[r0 + 0][k];
        float a1 = xs[r0 + 1][k];
        float a2 = xs[r0 + 2][k];
        float a3 = xs[r0 + 3][k];
        acc[0][0] += a0 * wv.x; acc[0][1] += a0 * wv.y; acc[0][2] += a0 * wv.z; acc[0][3] += a0 * wv.w;
        acc[1][0] += a1 * wv.x; acc[1][1] += a1 * wv.y; acc[1][2] += a1 * wv.z; acc[1][3] += a1 * wv.w;
        acc[2][0] += a2 * wv.x; acc[2][1] += a2 * wv.y; acc[2][2] += a2 * wv.z; acc[2][3] += a2 * wv.w;
        acc[3][0] += a3 * wv.x; acc[3][1] += a3 * wv.y; acc[3][2] += a3 * wv.z; acc[3][3] += a3 * wv.w;
    }

    float4 bv = *(const float4*)&b[c0];
#pragma unroll
    for (int i = 0; i < 4; i++) {
        int gr = row0 + r0 + i;
        if (gr >= n) break;
        float4 v;
        v.x = fmaxf(acc[i][0] + bv.x, 0.f);
        v.y = fmaxf(acc[i][1] + bv.y, 0.f);
        v.z = fmaxf(acc[i][2] + bv.z, 0.f);
        v.w = fmaxf(acc[i][3] + bv.w, 0.f);
        *(float4*)&g_x0 [gr * HID + c0] = v;
        *(float4*)&g_out[gr * HID + c0] = v;   // layer-0 node_pre reads g_out
    }
}

// ---------------- per-node pre-pass: h = BN(out), al/ar projections ----------------
// reads g_out, writes g_h / g_al / g_ar. One warp per node.
__global__ void k_node_pre(const float* __restrict__ attl,
                           const float* __restrict__ attr, int n) {
    int gt = blockIdx.x * blockDim.x + threadIdx.x;
    int node = gt >> 5, lane = threadIdx.x & 31;
    if (node >= n) return;
    int c0 = lane * 2;
    int base = node * HID + c0;
    float2 y = *(const float2*)&g_out[base];
    float h0 = y.x * g_scale[c0]     + g_shift[c0];
    float h1 = y.y * g_scale[c0 + 1] + g_shift[c0 + 1];
    *(float2*)&g_h[base] = make_float2(h0, h1);
    float a = h0 * attl[c0] + h1 * attl[c0 + 1];
    float r = h0 * attr[c0] + h1 * attr[c0 + 1];
#pragma unroll
    for (int o = 16; o; o >>= 1) {
        a += __shfl_xor_sync(0xffffffffu, a, o);
        r += __shfl_xor_sync(0xffffffffu, r, o);
    }
    if (lane == 0) { g_al[node] = a; g_ar[node] = r; }
}

// ---------------- per-edge weights in CSR order ----------------
__global__ void k_edgew(int E) {
    int p = blockIdx.x * blockDim.x + threadIdx.x;
    if (p >= E) return;
    int s = g_csrc[p];
    int d = g_cdst[p];
    g_w[p] = tanhf(g_al[s] + g_ar[d]) * g_dinv[s] * g_dinv[d];
}

// ---------------- aggregation: 16 threads/node, register accum, no atomics ----------
// out = relu( sum_in w*h[src] + selfw*h[node] + EPS*x0 ), writes g_out, BN stats.
__global__ __launch_bounds__(256) void k_agg(int n) {
    __shared__ float ssum[HID], ssq[HID];
    int tid = threadIdx.x;
    if (tid < HID) { ssum[tid] = 0.f; ssq[tid] = 0.f; }
    __syncthreads();
    int node = blockIdx.x * 16 + (tid >> 4);
    int q = tid & 15;
    if (node < n) {
        float4 acc = make_float4(0.f, 0.f, 0.f, 0.f);
        int p0 = g_off[node], p1 = g_off[node + 1];
#pragma unroll 4
        for (int p = p0; p < p1; p++) {
            int s = __ldg(&g_csrc[p]);
            float w = __ldg(&g_w[p]);
            float4 hv = *(const float4*)&g_h[s * HID + q * 4];
            acc.x += w * hv.x; acc.y += w * hv.y;
            acc.z += w * hv.z; acc.w += w * hv.w;
        }
        float dv = g_dinv[node];
        float ws = tanhf(g_al[node] + g_ar[node]) * dv * dv;
        int base = node * HID + q * 4;
        float4 hv  = *(const float4*)&g_h [base];
        float4 x0v = *(const float4*)&g_x0[base];
        float4 v;
        v.x = fmaxf(acc.x + ws * hv.x + EPS_RES * x0v.x, 0.f);
        v.y = fmaxf(acc.y + ws * hv.y + EPS_RES * x0v.y, 0.f);
        v.z = fmaxf(acc.z + ws * hv.z + EPS_RES * x0v.z, 0.f);
        v.w = fmaxf(acc.w + ws * hv.w + EPS_RES * x0v.w, 0.f);
        *(float4*)&g_out[base] = v;
        int c = q * 4;
        atomicAdd(&ssum[c + 0], v.x); atomicAdd(&ssum[c + 1], v.y);
        atomicAdd(&ssum[c + 2], v.z); atomicAdd(&ssum[c + 3], v.w);
        atomicAdd(&ssq[c + 0], v.x * v.x); atomicAdd(&ssq[c + 1], v.y * v.y);
        atomicAdd(&ssq[c + 2], v.z * v.z); atomicAdd(&ssq[c + 3], v.w * v.w);
    }
    __syncthreads();
    if (tid < HID) {
        atomicAdd(&g_stats[tid], ssum[tid]);
        atomicAdd(&g_stats[HID + tid], ssq[tid]);
    }
}

// ---------------- BN finalize: scale/shift from stats; re-zero stats ----------------
__global__ void k_finalize(const float* __restrict__ g, const float* __restrict__ b,
                           float inv_n) {
    int c = threadIdx.x;
    float mean = g_stats[c] * inv_n;
    float var = g_stats[HID + c] * inv_n - mean * mean;
    float sc = g[c] * rsqrtf(var + BN_EPS);
    g_scale[c] = sc;
    g_shift[c] = b[c] - mean * sc;
    g_stats[c] = 0.f;
    g_stats[HID + c] = 0.f;
}

// ---------------- head: t1 = bn3(y)[:bs] @ W1 + b1 ; stats (in g_out -> g_h) -------
__global__ void k_head1(const float* __restrict__ W1, const float* __restrict__ b1, int bs) {
    __shared__ float Ws[HID * HID];
    __shared__ float hs[4][HID];
    __shared__ float ssum[HID], ssq[HID];
    int tx = threadIdx.x, ty = threadIdx.y;
    int tid = ty * 64 + tx;
    for (int i = tid; i < HID * HID; i += 256) Ws[i] = W1[i];
    int row = blockIdx.x * 4 + ty;
    hs[ty][tx] = (row < bs) ? g_out[row * HID + tx] * g_scale[tx] + g_shift[tx] : 0.f;
    if (tid < HID) { ssum[tid] = 0.f; ssq[tid] = 0.f; }
    __syncthreads();
    float acc = b1[tx];
#pragma unroll
    for (int k = 0; k < HID; k++) acc += hs[ty][k] * Ws[k * HID + tx];
    if (row < bs) g_h[row * HID + tx] = acc; else acc = 0.f;
    atomicAdd(&ssum[tx], acc);
    atomicAdd(&ssq[tx], acc * acc);
    __syncthreads();
    if (tid < HID) {
        atomicAdd(&g_stats[tid], ssum[tid]);
        atomicAdd(&g_stats[HID + tid], ssq[tid]);
    }
}

// ---------------- head: t2 = relu(bn(t1)) @ W2 + b2 ; stats (g_h -> g_t2) ----------
__global__ void k_head2(const float* __restrict__ W2, const float* __restrict__ b2, int bs) {
    __shared__ float Ws[HID * 32];
    __shared__ float us[8][HID];
    __shared__ float ssum[32], ssq[32];
    int tx = threadIdx.x, ty = threadIdx.y;   // 32 x 8
    int tid = ty * 32 + tx;
    for (int i = tid; i < HID * 32; i += 256) Ws[i] = W2[i];
    int row = blockIdx.x * 8 + ty;
    if (row < bs) {
        float v0 = g_h[row * HID + tx]      * g_scale[tx]      + g_shift[tx];
        float v1 = g_h[row * HID + 32 + tx] * g_scale[32 + tx] + g_shift[32 + tx];
        us[ty][tx] = fmaxf(v0, 0.f);
        us[ty][32 + tx] = fmaxf(v1, 0.f);
    } else { us[ty][tx] = 0.f; us[ty][32 + tx] = 0.f; }
    if (tid < 32) { ssum[tid] = 0.f; ssq[tid] = 0.f; }
    __syncthreads();
    float acc = b2[tx];
#pragma unroll
    for (int k = 0; k < HID; k++) acc += us[ty][k] * Ws[k * 32 + tx];
    if (row < bs) g_t2[row * 32 + tx] = acc; else acc = 0.f;
    atomicAdd(&ssum[tx], acc);
    atomicAdd(&ssq[tx], acc * acc);
    __syncthreads();
    if (tid < 32) {
        atomicAdd(&g_stats[tid], ssum[tid]);
        atomicAdd(&g_stats[HID + tid], ssq[tid]);
    }
}

// ---------------- head: out = relu(bn(t2)) @ W3 + b3 ----------------
__global__ void k_head3(const float* __restrict__ W3, const float* __restrict__ b3,
                        float* __restrict__ out, int bs) {
    int gt = blockIdx.x * blockDim.x + threadIdx.x;
    int row = gt >> 5, lane = threadIdx.x & 31;
    if (row >= bs) return;
    float v = g_t2[row * 32 + lane] * g_scale[lane] + g_shift[lane];
    v = fmaxf(v, 0.f) * W3[lane];
#pragma unroll
    for (int o = 16; o; o >>= 1) v += __shfl_xor_sync(0xffffffffu, v, o);
    if (lane == 0) out[row] = v + b3[0];
}

extern "C" void kernel_launch(void* const* d_in, const int* in_sizes, int n_in,
                              void* d_out, int out_size) {
    const float* x    = (const float*)d_in[0];
    const int*   ei   = (const int*)d_in[1];
    int E = in_sizes[1] / 2;
    int n = in_sizes[0] / INCH;
    const float* W_in  = (const float*)d_in[3];
    const float* b_in  = (const float*)d_in[4];
    const float* att_l = (const float*)d_in[5];
    const float* att_r = (const float*)d_in[6];
    const float* bn_g  = (const float*)d_in[7];
    const float* bn_b  = (const float*)d_in[8];
    const float* W1  = (const float*)d_in[9];
    const float* b1  = (const float*)d_in[10];
    const float* g1  = (const float*)d_in[11];
    const float* be1 = (const float*)d_in[12];
    const float* W2  = (const float*)d_in[13];
    const float* b2  = (const float*)d_in[14];
    const float* g2  = (const float*)d_in[15];
    const float* be2 = (const float*)d_in[16];
    const float* W3  = (const float*)d_in[17];
    const float* b3  = (const float*)d_in[18];
    const int* src = ei;
    const int* dst = ei + E;
    int bs = out_size;   // output shape is (batch_size,)

    k_init<<<(n + 255) / 256, 256>>>(n);
    k_deg<<<(E + 255) / 256, 256>>>(dst, E);
    k_dinv<<<(n + 255) / 256, 256>>>(n);
    k_scan<<<1, 1024>>>(n);
    k_scatter<<<(E + 255) / 256, 256>>>(src, dst, E);
    k_ingemm<<<(n + 63) / 64, 256>>>(x, W_in, b_in, n);

    for (int l = 0; l < 3; l++) {
        k_node_pre<<<(n + 7) / 8, 256>>>(att_l + l * HID, att_r + l * HID, n);
        k_edgew<<<(E + 255) / 256, 256>>>(E);
        k_agg<<<(n + 15) / 16, 256>>>(n);
        k_finalize<<<1, HID>>>(bn_g + l * HID, bn_b + l * HID, 1.0f / n);
    }

    k_head1<<<(bs + 3) / 4, dim3(64, 4)>>>(W1, b1, bs);
    k_finalize<<<1, HID>>>(g1, be1, 1.0f / bs);
    k_head2<<<(bs + 7) / 8, dim3(32, 8)>>>(W2, b2, bs);
    k_finalize<<<1, 32>>>(g2, be2, 1.0f / bs);
    k_head3<<<(bs * 32 + 255) / 256, 256>>>(W3, b3, (float*)d_out, bs);
}

// round 5
// speedup vs baseline: 1.4935x; 1.1738x over previous
#include <cuda_runtime.h>

#define HID 64
#define INCH 128
#define NMAX 50000
#define EMAX 1200000
#define EPS_RES 0.1f
#define BN_EPS 1e-5f

// ---------------- scratch (device globals; no allocation) ----------------
__device__ __align__(128) float g_x0 [NMAX * HID];
__device__ __align__(128) float g_h  [NMAX * HID];
__device__ __align__(128) float g_out[NMAX * HID];
__device__ __align__(128) float g_t2 [NMAX * 32];
__device__ float g_al[NMAX];
__device__ float g_ar[NMAX];
__device__ float g_dinv[NMAX];
__device__ int   g_deg[NMAX];
__device__ int   g_off[NMAX];
__device__ int   g_cur[NMAX];
__device__ int   g_ctr;
__device__ int   g_csrc[EMAX];
__device__ int   g_cdst[EMAX];
__device__ float g_w[EMAX];
__device__ float g_stats[2 * HID];   // [0..63] col sums, [64..127] col sumsq
__device__ float g_scale[HID];
__device__ float g_shift[HID];

// ---------------- init ----------------
__global__ void k_init(int n) {
    int i = blockIdx.x * blockDim.x + threadIdx.x;
    if (i < n) { g_deg[i] = 1; g_cur[i] = 0; }      // self-loop counted in deg
    if (i < 2 * HID) g_stats[i] = 0.f;
    if (i < HID) { g_scale[i] = 1.f; g_shift[i] = 0.f; }
    if (i == 0) g_ctr = 0;
}

__global__ void k_deg(const int* __restrict__ dst, int E) {
    int e = blockIdx.x * blockDim.x + threadIdx.x;
    if (e < E) atomicAdd(&g_deg[dst[e]], 1);
}

// ---------------- CSR range allocation: warp-aggregated atomic, + dinv ------------
// Offsets need not be ordered — any disjoint assignment of [off, off+deg-1) works.
__global__ void k_off(int n) {
    int i = blockIdx.x * blockDim.x + threadIdx.x;
    int lane = threadIdx.x & 31;
    int deg = (i < n) ? g_deg[i] : 1;
    if (i < n) g_dinv[i] = rsqrtf((float)deg);
    int v = deg - 1;            // in-edges excluding self-loop
    int pre = v;
#pragma unroll
    for (int o = 1; o < 32; o <<= 1) {
        int t = __shfl_up_sync(0xffffffffu, pre, o);
        if (lane >= o) pre += t;
    }
    int base = 0;
    if (lane == 31) base = atomicAdd(&g_ctr, pre);   // pre at lane31 = warp total
    base = __shfl_sync(0xffffffffu, base, 31);
    if (i < n) g_off[i] = base + pre - v;            // exclusive within warp
}

// ---------------- scatter edges into CSR (grouped by dst) ----------------
__global__ void k_scatter(const int* __restrict__ src, const int* __restrict__ dst, int E) {
    int e = blockIdx.x * blockDim.x + threadIdx.x;
    if (e >= E) return;
    int d = dst[e];
    int pos = g_off[d] + atomicAdd(&g_cur[d], 1);
    g_csrc[pos] = src[e];
    g_cdst[pos] = d;
}

// ---------------- x0 = relu(x @ W_in + b_in); also seed g_out = x0 ----------------
__global__ __launch_bounds__(256) void k_ingemm(
        const float* __restrict__ x, const float* __restrict__ W,
        const float* __restrict__ b, int n) {
    __shared__ float Ws[INCH * HID];          // 32 KB, [k][col]
    __shared__ float xs[64][INCH];            // 32 KB
    int tid = threadIdx.x;
    int tx = tid & 15;
    int ty = tid >> 4;
    int row0 = blockIdx.x * 64;

    const float4* W4 = (const float4*)W;
    float4* Ws4 = (float4*)Ws;
    for (int i = tid; i < INCH * HID / 4; i += 256) Ws4[i] = W4[i];
    for (int i = tid; i < 64 * 32; i += 256) {
        int r = i >> 5, c4 = (i & 31) * 4;
        int gr = row0 + r;
        float4 v = (gr < n) ? *(const float4*)&x[gr * INCH + c4]
                            : make_float4(0.f, 0.f, 0.f, 0.f);
        *(float4*)&xs[r][c4] = v;
    }
    __syncthreads();

    float acc[4][4];
#pragma unroll
    for (int i = 0; i < 4; i++)
#pragma unroll
        for (int j = 0; j < 4; j++) acc[i][j] = 0.f;

    int r0 = ty * 4, c0 = tx * 4;
#pragma unroll 4
    for (int k = 0; k < INCH; k++) {
        float4 wv = *(const float4*)&Ws[k * HID + c0];
        float a0 = xs[r0 + 0][k];
        float a1 = xs[r0 + 1][k];
        float a2 = xs[r0 + 2][k];
        float a3 = xs[r0 + 3][k];
        acc[0][0] += a0 * wv.x; acc[0][1] += a0 * wv.y; acc[0][2] += a0 * wv.z; acc[0][3] += a0 * wv.w;
        acc[1][0] += a1 * wv.x; acc[1][1] += a1 * wv.y; acc[1][2] += a1 * wv.z; acc[1][3] += a1 * wv.w;
        acc[2][0] += a2 * wv.x; acc[2][1] += a2 * wv.y; acc[2][2] += a2 * wv.z; acc[2][3] += a2 * wv.w;
        acc[3][0] += a3 * wv.x; acc[3][1] += a3 * wv.y; acc[3][2] += a3 * wv.z; acc[3][3] += a3 * wv.w;
    }

    float4 bv = *(const float4*)&b[c0];
#pragma unroll
    for (int i = 0; i < 4; i++) {
        int gr = row0 + r0 + i;
        if (gr >= n) break;
        float4 v;
        v.x = fmaxf(acc[i][0] + bv.x, 0.f);
        v.y = fmaxf(acc[i][1] + bv.y, 0.f);
        v.z = fmaxf(acc[i][2] + bv.z, 0.f);
        v.w = fmaxf(acc[i][3] + bv.w, 0.f);
        *(float4*)&g_x0 [gr * HID + c0] = v;
        *(float4*)&g_out[gr * HID + c0] = v;   // layer-0 node_pre reads g_out
    }
}

// ---------------- per-node pre-pass: h = BN(out), al/ar projections ----------------
__global__ void k_node_pre(const float* __restrict__ attl,
                           const float* __restrict__ attr, int n) {
    int gt = blockIdx.x * blockDim.x + threadIdx.x;
    int node = gt >> 5, lane = threadIdx.x & 31;
    if (node >= n) return;
    int c0 = lane * 2;
    int base = node * HID + c0;
    float2 y = *(const float2*)&g_out[base];
    float h0 = y.x * g_scale[c0]     + g_shift[c0];
    float h1 = y.y * g_scale[c0 + 1] + g_shift[c0 + 1];
    *(float2*)&g_h[base] = make_float2(h0, h1);
    float a = h0 * attl[c0] + h1 * attl[c0 + 1];
    float r = h0 * attr[c0] + h1 * attr[c0 + 1];
#pragma unroll
    for (int o = 16; o; o >>= 1) {
        a += __shfl_xor_sync(0xffffffffu, a, o);
        r += __shfl_xor_sync(0xffffffffu, r, o);
    }
    if (lane == 0) { g_al[node] = a; g_ar[node] = r; }
}

// ---------------- per-edge weights in CSR order ----------------
__global__ void k_edgew(int E) {
    int p = blockIdx.x * blockDim.x + threadIdx.x;
    if (p >= E) return;
    int s = g_csrc[p];
    int d = g_cdst[p];
    g_w[p] = tanhf(g_al[s] + g_ar[d]) * g_dinv[s] * g_dinv[d];
}

// ---------------- aggregation: 16 threads/node, register accum, no atomics ----------
__global__ __launch_bounds__(256) void k_agg(int n) {
    __shared__ float ssum[HID], ssq[HID];
    int tid = threadIdx.x;
    if (tid < HID) { ssum[tid] = 0.f; ssq[tid] = 0.f; }
    __syncthreads();
    int node = blockIdx.x * 16 + (tid >> 4);
    int q = tid & 15;
    if (node < n) {
        float4 acc = make_float4(0.f, 0.f, 0.f, 0.f);
        int p0 = g_off[node];
        int p1 = p0 + g_deg[node] - 1;
#pragma unroll 4
        for (int p = p0; p < p1; p++) {
            int s = __ldg(&g_csrc[p]);
            float w = __ldg(&g_w[p]);
            float4 hv = *(const float4*)&g_h[s * HID + q * 4];
            acc.x += w * hv.x; acc.y += w * hv.y;
            acc.z += w * hv.z; acc.w += w * hv.w;
        }
        float dv = g_dinv[node];
        float ws = tanhf(g_al[node] + g_ar[node]) * dv * dv;
        int base = node * HID + q * 4;
        float4 hv  = *(const float4*)&g_h [base];
        float4 x0v = *(const float4*)&g_x0[base];
        float4 v;
        v.x = fmaxf(acc.x + ws * hv.x + EPS_RES * x0v.x, 0.f);
        v.y = fmaxf(acc.y + ws * hv.y + EPS_RES * x0v.y, 0.f);
        v.z = fmaxf(acc.z + ws * hv.z + EPS_RES * x0v.z, 0.f);
        v.w = fmaxf(acc.w + ws * hv.w + EPS_RES * x0v.w, 0.f);
        *(float4*)&g_out[base] = v;
        int c = q * 4;
        atomicAdd(&ssum[c + 0], v.x); atomicAdd(&ssum[c + 1], v.y);
        atomicAdd(&ssum[c + 2], v.z); atomicAdd(&ssum[c + 3], v.w);
        atomicAdd(&ssq[c + 0], v.x * v.x); atomicAdd(&ssq[c + 1], v.y * v.y);
        atomicAdd(&ssq[c + 2], v.z * v.z); atomicAdd(&ssq[c + 3], v.w * v.w);
    }
    __syncthreads();
    if (tid < HID) {
        atomicAdd(&g_stats[tid], ssum[tid]);
        atomicAdd(&g_stats[HID + tid], ssq[tid]);
    }
}

// ---------------- BN finalize ----------------
__global__ void k_finalize(const float* __restrict__ g, const float* __restrict__ b,
                           float inv_n) {
    int c = threadIdx.x;
    float mean = g_stats[c] * inv_n;
    float var = g_stats[HID + c] * inv_n - mean * mean;
    float sc = g[c] * rsqrtf(var + BN_EPS);
    g_scale[c] = sc;
    g_shift[c] = b[c] - mean * sc;
    g_stats[c] = 0.f;
    g_stats[HID + c] = 0.f;
}

// ---------------- head: t1 = bn3(y)[:bs] @ W1 + b1 ; stats (g_out -> g_h) ----------
__global__ void k_head1(const float* __restrict__ W1, const float* __restrict__ b1, int bs) {
    __shared__ float Ws[HID * HID];
    __shared__ float hs[4][HID];
    __shared__ float ssum[HID], ssq[HID];
    int tx = threadIdx.x, ty = threadIdx.y;
    int tid = ty * 64 + tx;
    for (int i = tid; i < HID * HID; i += 256) Ws[i] = W1[i];
    int row = blockIdx.x * 4 + ty;
    hs[ty][tx] = (row < bs) ? g_out[row * HID + tx] * g_scale[tx] + g_shift[tx] : 0.f;
    if (tid < HID) { ssum[tid] = 0.f; ssq[tid] = 0.f; }
    __syncthreads();
    float acc = b1[tx];
#pragma unroll
    for (int k = 0; k < HID; k++) acc += hs[ty][k] * Ws[k * HID + tx];
    if (row < bs) g_h[row * HID + tx] = acc; else acc = 0.f;
    atomicAdd(&ssum[tx], acc);
    atomicAdd(&ssq[tx], acc * acc);
    __syncthreads();
    if (tid < HID) {
        atomicAdd(&g_stats[tid], ssum[tid]);
        atomicAdd(&g_stats[HID + tid], ssq[tid]);
    }
}

// ---------------- head: t2 = relu(bn(t1)) @ W2 + b2 ; stats (g_h -> g_t2) ----------
__global__ void k_head2(const float* __restrict__ W2, const float* __restrict__ b2, int bs) {
    __shared__ float Ws[HID * 32];
    __shared__ float us[8][HID];
    __shared__ float ssum[32], ssq[32];
    int tx = threadIdx.x, ty = threadIdx.y;   // 32 x 8
    int tid = ty * 32 + tx;
    for (int i = tid; i < HID * 32; i += 256) Ws[i] = W2[i];
    int row = blockIdx.x * 8 + ty;
    if (row < bs) {
        float v0 = g_h[row * HID + tx]      * g_scale[tx]      + g_shift[tx];
        float v1 = g_h[row * HID + 32 + tx] * g_scale[32 + tx] + g_shift[32 + tx];
        us[ty][tx] = fmaxf(v0, 0.f);
        us[ty][32 + tx] = fmaxf(v1, 0.f);
    } else { us[ty][tx] = 0.f; us[ty][32 + tx] = 0.f; }
    if (tid < 32) { ssum[tid] = 0.f; ssq[tid] = 0.f; }
    __syncthreads();
    float acc = b2[tx];
#pragma unroll
    for (int k = 0; k < HID; k++) acc += us[ty][k] * Ws[k * 32 + tx];
    if (row < bs) g_t2[row * 32 + tx] = acc; else acc = 0.f;
    atomicAdd(&ssum[tx], acc);
    atomicAdd(&ssq[tx], acc * acc);
    __syncthreads();
    if (tid < 32) {
        atomicAdd(&g_stats[tid], ssum[tid]);
        atomicAdd(&g_stats[HID + tid], ssq[tid]);
    }
}

// ---------------- head: out = relu(bn(t2)) @ W3 + b3 ----------------
__global__ void k_head3(const float* __restrict__ W3, const float* __restrict__ b3,
                        float* __restrict__ out, int bs) {
    int gt = blockIdx.x * blockDim.x + threadIdx.x;
    int row = gt >> 5, lane = threadIdx.x & 31;
    if (row >= bs) return;
    float v = g_t2[row * 32 + lane] * g_scale[lane] + g_shift[lane];
    v = fmaxf(v, 0.f) * W3[lane];
#pragma unroll
    for (int o = 16; o; o >>= 1) v += __shfl_xor_sync(0xffffffffu, v, o);
    if (lane == 0) out[row] = v + b3[0];
}

extern "C" void kernel_launch(void* const* d_in, const int* in_sizes, int n_in,
                              void* d_out, int out_size) {
    const float* x    = (const float*)d_in[0];
    const int*   ei   = (const int*)d_in[1];
    int E = in_sizes[1] / 2;
    int n = in_sizes[0] / INCH;
    const float* W_in  = (const float*)d_in[3];
    const float* b_in  = (const float*)d_in[4];
    const float* att_l = (const float*)d_in[5];
    const float* att_r = (const float*)d_in[6];
    const float* bn_g  = (const float*)d_in[7];
    const float* bn_b  = (const float*)d_in[8];
    const float* W1  = (const float*)d_in[9];
    const float* b1  = (const float*)d_in[10];
    const float* g1  = (const float*)d_in[11];
    const float* be1 = (const float*)d_in[12];
    const float* W2  = (const float*)d_in[13];
    const float* b2  = (const float*)d_in[14];
    const float* g2  = (const float*)d_in[15];
    const float* be2 = (const float*)d_in[16];
    const float* W3  = (const float*)d_in[17];
    const float* b3  = (const float*)d_in[18];
    const int* src = ei;
    const int* dst = ei + E;
    int bs = out_size;   // output shape is (batch_size,)

    k_init<<<(n + 255) / 256, 256>>>(n);
    k_deg<<<(E + 255) / 256, 256>>>(dst, E);
    k_off<<<(n + 255) / 256, 256>>>(n);
    k_scatter<<<(E + 255) / 256, 256>>>(src, dst, E);
    k_ingemm<<<(n + 63) / 64, 256>>>(x, W_in, b_in, n);

    for (int l = 0; l < 3; l++) {
        k_node_pre<<<(n + 7) / 8, 256>>>(att_l + l * HID, att_r + l * HID, n);
        k_edgew<<<(E + 255) / 256, 256>>>(E);
        k_agg<<<(n + 15) / 16, 256>>>(n);
        k_finalize<<<1, HID>>>(bn_g + l * HID, bn_b + l * HID, 1.0f / n);
    }

    k_head1<<<(bs + 3) / 4, dim3(64, 4)>>>(W1, b1, bs);
    k_finalize<<<1, HID>>>(g1, be1, 1.0f / bs);
    k_head2<<<(bs + 7) / 8, dim3(32, 8)>>>(W2, b2, bs);
    k_finalize<<<1, 32>>>(g2, be2, 1.0f / bs);
    k_head3<<<(bs * 32 + 255) / 256, 256>>>(W3, b3, (float*)d_out, bs);
}

// round 7
// speedup vs baseline: 1.5795x; 1.0576x over previous
#include <cuda_runtime.h>

#define HID 64
#define INCH 128
#define NMAX 50000
#define EMAX 1200000
#define EPS_RES 0.1f
#define BN_EPS 1e-5f

// ---------------- scratch (device globals; no allocation) ----------------
__device__ __align__(128) float g_x0 [NMAX * HID];
__device__ __align__(128) float g_h  [NMAX * HID];
__device__ __align__(128) float g_out[NMAX * HID];
__device__ __align__(128) float g_t2 [NMAX * 32];
__device__ __align__(8) float2 g_sv[NMAX];   // (al[node], dinv[node])
__device__ float g_ar[NMAX];
__device__ float g_dinv[NMAX];
__device__ int   g_deg[NMAX];
__device__ int   g_off[NMAX];
__device__ int   g_cur[NMAX];
__device__ int   g_ctr;
__device__ int   g_csrc[EMAX];
__device__ float g_stats[2 * HID];   // [0..63] col sums, [64..127] col sumsq
__device__ float g_scale[HID];
__device__ float g_shift[HID];

// ---------------- init ----------------
__global__ void k_init(int n) {
    int i = blockIdx.x * blockDim.x + threadIdx.x;
    if (i < n) { g_deg[i] = 1; g_cur[i] = 0; }      // self-loop counted in deg
    if (i < 2 * HID) g_stats[i] = 0.f;
    if (i < HID) { g_scale[i] = 1.f; g_shift[i] = 0.f; }
    if (i == 0) g_ctr = 0;
}

__global__ void k_deg(const int* __restrict__ dst, int E) {
    int e = blockIdx.x * blockDim.x + threadIdx.x;
    if (e < E) atomicAdd(&g_deg[dst[e]], 1);
}

// ---------------- CSR range allocation: warp-aggregated atomic, + dinv ------------
__global__ void k_off(int n) {
    int i = blockIdx.x * blockDim.x + threadIdx.x;
    int lane = threadIdx.x & 31;
    int deg = (i < n) ? g_deg[i] : 1;
    if (i < n) g_dinv[i] = rsqrtf((float)deg);
    int v = deg - 1;            // in-edges excluding self-loop
    int pre = v;
#pragma unroll
    for (int o = 1; o < 32; o <<= 1) {
        int t = __shfl_up_sync(0xffffffffu, pre, o);
        if (lane >= o) pre += t;
    }
    int base = 0;
    if (lane == 31) base = atomicAdd(&g_ctr, pre);   // pre at lane31 = warp total
    base = __shfl_sync(0xffffffffu, base, 31);
    if (i < n) g_off[i] = base + pre - v;            // exclusive within warp
}

// ---------------- scatter edges into CSR (grouped by dst), src only --------------
__global__ void k_scatter(const int* __restrict__ src, const int* __restrict__ dst, int E) {
    int e = blockIdx.x * blockDim.x + threadIdx.x;
    if (e >= E) return;
    int d = dst[e];
    int pos = g_off[d] + atomicAdd(&g_cur[d], 1);
    g_csrc[pos] = src[e];
}

// ---------------- x0 = relu(x @ W_in + b_in); also seed g_out = x0 ----------------
__global__ __launch_bounds__(256) void k_ingemm(
        const float* __restrict__ x, const float* __restrict__ W,
        const float* __restrict__ b, int n) {
    __shared__ float Ws[INCH * HID];          // 32 KB, [k][col]
    __shared__ float xs[64][INCH];            // 32 KB
    int tid = threadIdx.x;
    int tx = tid & 15;
    int ty = tid >> 4;
    int row0 = blockIdx.x * 64;

    const float4* W4 = (const float4*)W;
    float4* Ws4 = (float4*)Ws;
    for (int i = tid; i < INCH * HID / 4; i += 256) Ws4[i] = W4[i];
    for (int i = tid; i < 64 * 32; i += 256) {
        int r = i >> 5, c4 = (i & 31) * 4;
        int gr = row0 + r;
        float4 v = (gr < n) ? *(const float4*)&x[gr * INCH + c4]
                            : make_float4(0.f, 0.f, 0.f, 0.f);
        *(float4*)&xs[r][c4] = v;
    }
    __syncthreads();

    float acc[4][4];
#pragma unroll
    for (int i = 0; i < 4; i++)
#pragma unroll
        for (int j = 0; j < 4; j++) acc[i][j] = 0.f;

    int r0 = ty * 4, c0 = tx * 4;
#pragma unroll 4
    for (int k = 0; k < INCH; k++) {
        float4 wv = *(const float4*)&Ws[k * HID + c0];
        float a0 = xs[r0 + 0][k];
        float a1 = xs[r0 + 1][k];
        float a2 = xs[r0 + 2][k];
        float a3 = xs[r0 + 3][k];
        acc[0][0] += a0 * wv.x; acc[0][1] += a0 * wv.y; acc[0][2] += a0 * wv.z; acc[0][3] += a0 * wv.w;
        acc[1][0] += a1 * wv.x; acc[1][1] += a1 * wv.y; acc[1][2] += a1 * wv.z; acc[1][3] += a1 * wv.w;
        acc[2][0] += a2 * wv.x; acc[2][1] += a2 * wv.y; acc[2][2] += a2 * wv.z; acc[2][3] += a2 * wv.w;
        acc[3][0] += a3 * wv.x; acc[3][1] += a3 * wv.y; acc[3][2] += a3 * wv.z; acc[3][3] += a3 * wv.w;
    }

    float4 bv = *(const float4*)&b[c0];
#pragma unroll
    for (int i = 0; i < 4; i++) {
        int gr = row0 + r0 + i;
        if (gr >= n) break;
        float4 v;
        v.x = fmaxf(acc[i][0] + bv.x, 0.f);
        v.y = fmaxf(acc[i][1] + bv.y, 0.f);
        v.z = fmaxf(acc[i][2] + bv.z, 0.f);
        v.w = fmaxf(acc[i][3] + bv.w, 0.f);
        *(float4*)&g_x0 [gr * HID + c0] = v;
        *(float4*)&g_out[gr * HID + c0] = v;   // layer-0 node_pre reads g_out
    }
}

// ---------------- per-node pre-pass: h = BN(out), al/ar projections ----------------
__global__ void k_node_pre(const float* __restrict__ attl,
                           const float* __restrict__ attr, int n) {
    int gt = blockIdx.x * blockDim.x + threadIdx.x;
    int node = gt >> 5, lane = threadIdx.x & 31;
    if (node >= n) return;
    int c0 = lane * 2;
    int base = node * HID + c0;
    float2 y = *(const float2*)&g_out[base];
    float h0 = y.x * g_scale[c0]     + g_shift[c0];
    float h1 = y.y * g_scale[c0 + 1] + g_shift[c0 + 1];
    *(float2*)&g_h[base] = make_float2(h0, h1);
    float a = h0 * attl[c0] + h1 * attl[c0 + 1];
    float r = h0 * attr[c0] + h1 * attr[c0 + 1];
#pragma unroll
    for (int o = 16; o; o >>= 1) {
        a += __shfl_xor_sync(0xffffffffu, a, o);
        r += __shfl_xor_sync(0xffffffffu, r, o);
    }
    if (lane == 0) {
        g_ar[node] = r;
        g_sv[node] = make_float2(a, g_dinv[node]);   // (al, dinv) packed
    }
}

// ---------------- aggregation: 16 threads/node, fused edge weights, no atomics -----
// Chunked: each thread computes w for one edge of the chunk (one tanh/edge),
// then the 16-group broadcasts (s, w) via group-masked shfl while gathering.
// CRITICAL: shfl mask is the 16-group only — the two groups of a warp have
// different loop trip counts, so a full-warp mask would deadlock.
__global__ __launch_bounds__(256) void k_agg(int n) {
    __shared__ float ssum[HID], ssq[HID];
    int tid = threadIdx.x;
    if (tid < HID) { ssum[tid] = 0.f; ssq[tid] = 0.f; }
    __syncthreads();
    int node = blockIdx.x * 16 + (tid >> 4);
    int q = tid & 15;
    unsigned gmask = 0xFFFFu << (tid & 16);   // this 16-group's lanes
    if (node < n) {
        float4 acc = make_float4(0.f, 0.f, 0.f, 0.f);
        int p0 = g_off[node];
        int p1 = p0 + g_deg[node] - 1;
        float dvd = g_dinv[node];
        float ard = g_ar[node];
        for (int chunk = p0; chunk < p1; chunk += 16) {
            int p = chunk + q;
            float wq = 0.f; int sq = 0;
            if (p < p1) {
                sq = __ldg(&g_csrc[p]);
                float2 sv = *(const float2*)&g_sv[sq];
                wq = tanhf(sv.x + ard) * sv.y * dvd;
            }
            int m = min(16, p1 - chunk);
            for (int j = 0; j < m; j++) {
                int s   = __shfl_sync(gmask, sq, j, 16);
                float w = __shfl_sync(gmask, wq, j, 16);
                float4 hv = *(const float4*)&g_h[s * HID + q * 4];
                acc.x += w * hv.x; acc.y += w * hv.y;
                acc.z += w * hv.z; acc.w += w * hv.w;
            }
        }
        float2 svn = g_sv[node];
        float ws = tanhf(svn.x + ard) * dvd * dvd;
        int base = node * HID + q * 4;
        float4 hv  = *(const float4*)&g_h [base];
        float4 x0v = *(const float4*)&g_x0[base];
        float4 v;
        v.x = fmaxf(acc.x + ws * hv.x + EPS_RES * x0v.x, 0.f);
        v.y = fmaxf(acc.y + ws * hv.y + EPS_RES * x0v.y, 0.f);
        v.z = fmaxf(acc.z + ws * hv.z + EPS_RES * x0v.z, 0.f);
        v.w = fmaxf(acc.w + ws * hv.w + EPS_RES * x0v.w, 0.f);
        *(float4*)&g_out[base] = v;
        int c = q * 4;
        atomicAdd(&ssum[c + 0], v.x); atomicAdd(&ssum[c + 1], v.y);
        atomicAdd(&ssum[c + 2], v.z); atomicAdd(&ssum[c + 3], v.w);
        atomicAdd(&ssq[c + 0], v.x * v.x); atomicAdd(&ssq[c + 1], v.y * v.y);
        atomicAdd(&ssq[c + 2], v.z * v.z); atomicAdd(&ssq[c + 3], v.w * v.w);
    }
    __syncthreads();
    if (tid < HID) {
        atomicAdd(&g_stats[tid], ssum[tid]);
        atomicAdd(&g_stats[HID + tid], ssq[tid]);
    }
}

// ---------------- BN finalize ----------------
__global__ void k_finalize(const float* __restrict__ g, const float* __restrict__ b,
                           float inv_n) {
    int c = threadIdx.x;
    float mean = g_stats[c] * inv_n;
    float var = g_stats[HID + c] * inv_n - mean * mean;
    float sc = g[c] * rsqrtf(var + BN_EPS);
    g_scale[c] = sc;
    g_shift[c] = b[c] - mean * sc;
    g_stats[c] = 0.f;
    g_stats[HID + c] = 0.f;
}

// ---------------- head: t1 = bn3(y)[:bs] @ W1 + b1 ; stats (g_out -> g_h) ----------
__global__ void k_head1(const float* __restrict__ W1, const float* __restrict__ b1, int bs) {
    __shared__ float Ws[HID * HID];
    __shared__ float hs[4][HID];
    __shared__ float ssum[HID], ssq[HID];
    int tx = threadIdx.x, ty = threadIdx.y;
    int tid = ty * 64 + tx;
    for (int i = tid; i < HID * HID; i += 256) Ws[i] = W1[i];
    int row = blockIdx.x * 4 + ty;
    hs[ty][tx] = (row < bs) ? g_out[row * HID + tx] * g_scale[tx] + g_shift[tx] : 0.f;
    if (tid < HID) { ssum[tid] = 0.f; ssq[tid] = 0.f; }
    __syncthreads();
    float acc = b1[tx];
#pragma unroll
    for (int k = 0; k < HID; k++) acc += hs[ty][k] * Ws[k * HID + tx];
    if (row < bs) g_h[row * HID + tx] = acc; else acc = 0.f;
    atomicAdd(&ssum[tx], acc);
    atomicAdd(&ssq[tx], acc * acc);
    __syncthreads();
    if (tid < HID) {
        atomicAdd(&g_stats[tid], ssum[tid]);
        atomicAdd(&g_stats[HID + tid], ssq[tid]);
    }
}

// ---------------- head: t2 = relu(bn(t1)) @ W2 + b2 ; stats (g_h -> g_t2) ----------
__global__ void k_head2(const float* __restrict__ W2, const float* __restrict__ b2, int bs) {
    __shared__ float Ws[HID * 32];
    __shared__ float us[8][HID];
    __shared__ float ssum[32], ssq[32];
    int tx = threadIdx.x, ty = threadIdx.y;   // 32 x 8
    int tid = ty * 32 + tx;
    for (int i = tid; i < HID * 32; i += 256) Ws[i] = W2[i];
    int row = blockIdx.x * 8 + ty;
    if (row < bs) {
        float v0 = g_h[row * HID + tx]      * g_scale[tx]      + g_shift[tx];
        float v1 = g_h[row * HID + 32 + tx] * g_scale[32 + tx] + g_shift[32 + tx];
        us[ty][tx] = fmaxf(v0, 0.f);
        us[ty][32 + tx] = fmaxf(v1, 0.f);
    } else { us[ty][tx] = 0.f; us[ty][32 + tx] = 0.f; }
    if (tid < 32) { ssum[tid] = 0.f; ssq[tid] = 0.f; }
    __syncthreads();
    float acc = b2[tx];
#pragma unroll
    for (int k = 0; k < HID; k++) acc += us[ty][k] * Ws[k * 32 + tx];
    if (row < bs) g_t2[row * 32 + tx] = acc; else acc = 0.f;
    atomicAdd(&ssum[tx], acc);
    atomicAdd(&ssq[tx], acc * acc);
    __syncthreads();
    if (tid < 32) {
        atomicAdd(&g_stats[tid], ssum[tid]);
        atomicAdd(&g_stats[HID + tid], ssq[tid]);
    }
}

// ---------------- head: out = relu(bn(t2)) @ W3 + b3 ----------------
__global__ void k_head3(const float* __restrict__ W3, const float* __restrict__ b3,
                        float* __restrict__ out, int bs) {
    int gt = blockIdx.x * blockDim.x + threadIdx.x;
    int row = gt >> 5, lane = threadIdx.x & 31;
    if (row >= bs) return;
    float v = g_t2[row * 32 + lane] * g_scale[lane] + g_shift[lane];
    v = fmaxf(v, 0.f) * W3[lane];
#pragma unroll
    for (int o = 16; o; o >>= 1) v += __shfl_xor_sync(0xffffffffu, v, o);
    if (lane == 0) out[row] = v + b3[0];
}

extern "C" void kernel_launch(void* const* d_in, const int* in_sizes, int n_in,
                              void* d_out, int out_size) {
    const float* x    = (const float*)d_in[0];
    const int*   ei   = (const int*)d_in[1];
    int E = in_sizes[1] / 2;
    int n = in_sizes[0] / INCH;
    const float* W_in  = (const float*)d_in[3];
    const float* b_in  = (const float*)d_in[4];
    const float* att_l = (const float*)d_in[5];
    const float* att_r = (const float*)d_in[6];
    const float* bn_g  = (const float*)d_in[7];
    const float* bn_b  = (const float*)d_in[8];
    const float* W1  = (const float*)d_in[9];
    const float* b1  = (const float*)d_in[10];
    const float* g1  = (const float*)d_in[11];
    const float* be1 = (const float*)d_in[12];
    const float* W2  = (const float*)d_in[13];
    const float* b2  = (const float*)d_in[14];
    const float* g2  = (const float*)d_in[15];
    const float* be2 = (const float*)d_in[16];
    const float* W3  = (const float*)d_in[17];
    const float* b3  = (const float*)d_in[18];
    const int* src = ei;
    const int* dst = ei + E;
    int bs = out_size;   // output shape is (batch_size,)

    k_init<<<(n + 255) / 256, 256>>>(n);
    k_deg<<<(E + 255) / 256, 256>>>(dst, E);
    k_off<<<(n + 255) / 256, 256>>>(n);
    k_scatter<<<(E + 255) / 256, 256>>>(src, dst, E);
    k_ingemm<<<(n + 63) / 64, 256>>>(x, W_in, b_in, n);

    for (int l = 0; l < 3; l++) {
        k_node_pre<<<(n + 7) / 8, 256>>>(att_l + l * HID, att_r + l * HID, n);
        k_agg<<<(n + 15) / 16, 256>>>(n);
        k_finalize<<<1, HID>>>(bn_g + l * HID, bn_b + l * HID, 1.0f / n);
    }

    k_head1<<<(bs + 3) / 4, dim3(64, 4)>>>(W1, b1, bs);
    k_finalize<<<1, HID>>>(g1, be1, 1.0f / bs);
    k_head2<<<(bs + 7) / 8, dim3(32, 8)>>>(W2, b2, bs);
    k_finalize<<<1, 32>>>(g2, be2, 1.0f / bs);
    k_head3<<<(bs * 32 + 255) / 256, 256>>>(W3, b3, (float*)d_out, bs);
}

// round 8
// speedup vs baseline: 1.6679x; 1.0559x over previous
#include <cuda_runtime.h>

#define HID 64
#define INCH 128
#define NMAX 50000
#define EMAX 1200000
#define EPS_RES 0.1f
#define BN_EPS 1e-5f

// ---------------- scratch (device globals; no allocation) ----------------
__device__ __align__(128) float g_x0 [NMAX * HID];
__device__ __align__(128) float g_h  [NMAX * HID];
__device__ __align__(128) float g_out[NMAX * HID];
__device__ __align__(128) float g_t2 [NMAX * 32];
__device__ __align__(8) float2 g_sv[NMAX];   // (al[node], dinv[node])
__device__ float g_ar[NMAX];
__device__ float g_dinv[NMAX];
__device__ int   g_deg[NMAX];
__device__ int   g_off[NMAX];
__device__ int   g_cur[NMAX];
__device__ int   g_ctr;
__device__ int   g_csrc[EMAX];
__device__ float g_stats[2 * HID];   // [0..63] col sums, [64..127] col sumsq
__device__ float g_scale[HID];
__device__ float g_shift[HID];

// ---------------- init ----------------
__global__ void k_init(int n) {
    int i = blockIdx.x * blockDim.x + threadIdx.x;
    if (i < n) { g_deg[i] = 1; g_cur[i] = 0; }      // self-loop counted in deg
    if (i < 2 * HID) g_stats[i] = 0.f;
    if (i < HID) { g_scale[i] = 1.f; g_shift[i] = 0.f; }
    if (i == 0) g_ctr = 0;
}

__global__ void k_deg(const int* __restrict__ dst, int E) {
    int e = blockIdx.x * blockDim.x + threadIdx.x;
    if (e < E) atomicAdd(&g_deg[dst[e]], 1);
}

// ---------------- CSR range allocation: warp-aggregated atomic, + dinv ------------
__global__ void k_off(int n) {
    int i = blockIdx.x * blockDim.x + threadIdx.x;
    int lane = threadIdx.x & 31;
    int deg = (i < n) ? g_deg[i] : 1;
    if (i < n) g_dinv[i] = rsqrtf((float)deg);
    int v = deg - 1;            // in-edges excluding self-loop
    int pre = v;
#pragma unroll
    for (int o = 1; o < 32; o <<= 1) {
        int t = __shfl_up_sync(0xffffffffu, pre, o);
        if (lane >= o) pre += t;
    }
    int base = 0;
    if (lane == 31) base = atomicAdd(&g_ctr, pre);   // pre at lane31 = warp total
    base = __shfl_sync(0xffffffffu, base, 31);
    if (i < n) g_off[i] = base + pre - v;            // exclusive within warp
}

// ---------------- scatter edges into CSR (grouped by dst), src only --------------
__global__ void k_scatter(const int* __restrict__ src, const int* __restrict__ dst, int E) {
    int e = blockIdx.x * blockDim.x + threadIdx.x;
    if (e >= E) return;
    int d = dst[e];
    int pos = g_off[d] + atomicAdd(&g_cur[d], 1);
    g_csrc[pos] = src[e];
}

// ---------------- x0 = relu(x @ W_in + b_in); also seed g_out = x0 ----------------
__global__ __launch_bounds__(256) void k_ingemm(
        const float* __restrict__ x, const float* __restrict__ W,
        const float* __restrict__ b, int n) {
    __shared__ float Ws[INCH * HID];          // 32 KB, [k][col]
    __shared__ float xs[64][INCH];            // 32 KB
    int tid = threadIdx.x;
    int tx = tid & 15;
    int ty = tid >> 4;
    int row0 = blockIdx.x * 64;

    const float4* W4 = (const float4*)W;
    float4* Ws4 = (float4*)Ws;
    for (int i = tid; i < INCH * HID / 4; i += 256) Ws4[i] = W4[i];
    for (int i = tid; i < 64 * 32; i += 256) {
        int r = i >> 5, c4 = (i & 31) * 4;
        int gr = row0 + r;
        float4 v = (gr < n) ? *(const float4*)&x[gr * INCH + c4]
                            : make_float4(0.f, 0.f, 0.f, 0.f);
        *(float4*)&xs[r][c4] = v;
    }
    __syncthreads();

    float acc[4][4];
#pragma unroll
    for (int i = 0; i < 4; i++)
#pragma unroll
        for (int j = 0; j < 4; j++) acc[i][j] = 0.f;

    int r0 = ty * 4, c0 = tx * 4;
#pragma unroll 4
    for (int k = 0; k < INCH; k++) {
        float4 wv = *(const float4*)&Ws[k * HID + c0];
        float a0 = xs[r0 + 0][k];
        float a1 = xs[r0 + 1][k];
        float a2 = xs[r0 + 2][k];
        float a3 = xs[r0 + 3][k];
        acc[0][0] += a0 * wv.x; acc[0][1] += a0 * wv.y; acc[0][2] += a0 * wv.z; acc[0][3] += a0 * wv.w;
        acc[1][0] += a1 * wv.x; acc[1][1] += a1 * wv.y; acc[1][2] += a1 * wv.z; acc[1][3] += a1 * wv.w;
        acc[2][0] += a2 * wv.x; acc[2][1] += a2 * wv.y; acc[2][2] += a2 * wv.z; acc[2][3] += a2 * wv.w;
        acc[3][0] += a3 * wv.x; acc[3][1] += a3 * wv.y; acc[3][2] += a3 * wv.z; acc[3][3] += a3 * wv.w;
    }

    float4 bv = *(const float4*)&b[c0];
#pragma unroll
    for (int i = 0; i < 4; i++) {
        int gr = row0 + r0 + i;
        if (gr >= n) break;
        float4 v;
        v.x = fmaxf(acc[i][0] + bv.x, 0.f);
        v.y = fmaxf(acc[i][1] + bv.y, 0.f);
        v.z = fmaxf(acc[i][2] + bv.z, 0.f);
        v.w = fmaxf(acc[i][3] + bv.w, 0.f);
        *(float4*)&g_x0 [gr * HID + c0] = v;
        *(float4*)&g_out[gr * HID + c0] = v;   // layer-0 node_pre reads g_out
    }
}

// ---------------- per-node pre-pass: 16 threads/node, float4 ----------------
// h = BN(out); al/ar projections via group-masked reduction.
__global__ void k_node_pre(const float* __restrict__ attl,
                           const float* __restrict__ attr, int n) {
    int gt = blockIdx.x * blockDim.x + threadIdx.x;
    int node = gt >> 4, q = threadIdx.x & 15;
    unsigned gmask = 0xFFFFu << (threadIdx.x & 16);
    if (node >= n) return;
    int c0 = q * 4;
    int base = node * HID + c0;
    float4 y  = *(const float4*)&g_out[base];
    float4 sc = *(const float4*)&g_scale[c0];
    float4 sh = *(const float4*)&g_shift[c0];
    float4 h;
    h.x = y.x * sc.x + sh.x;
    h.y = y.y * sc.y + sh.y;
    h.z = y.z * sc.z + sh.z;
    h.w = y.w * sc.w + sh.w;
    *(float4*)&g_h[base] = h;
    float4 al4 = *(const float4*)&attl[c0];
    float4 ar4 = *(const float4*)&attr[c0];
    float a = h.x * al4.x + h.y * al4.y + h.z * al4.z + h.w * al4.w;
    float r = h.x * ar4.x + h.y * ar4.y + h.z * ar4.z + h.w * ar4.w;
#pragma unroll
    for (int o = 8; o; o >>= 1) {
        a += __shfl_xor_sync(gmask, a, o, 16);
        r += __shfl_xor_sync(gmask, r, o, 16);
    }
    if (q == 0) {
        g_ar[node] = r;
        g_sv[node] = make_float2(a, g_dinv[node]);   // (al, dinv) packed
    }
}

// ---------------- aggregation: 16 threads/node, fused edge weights, no atomics -----
__global__ __launch_bounds__(256) void k_agg(int n) {
    __shared__ float ssum[HID], ssq[HID];
    int tid = threadIdx.x;
    if (tid < HID) { ssum[tid] = 0.f; ssq[tid] = 0.f; }
    __syncthreads();
    int node = blockIdx.x * 16 + (tid >> 4);
    int q = tid & 15;
    unsigned gmask = 0xFFFFu << (tid & 16);   // this 16-group's lanes
    if (node < n) {
        float4 acc = make_float4(0.f, 0.f, 0.f, 0.f);
        int p0 = g_off[node];
        int p1 = p0 + g_deg[node] - 1;
        float dvd = g_dinv[node];
        float ard = g_ar[node];
        for (int chunk = p0; chunk < p1; chunk += 16) {
            int p = chunk + q;
            float wq = 0.f; int sq = 0;
            if (p < p1) {
                sq = __ldg(&g_csrc[p]);
                float2 sv = *(const float2*)&g_sv[sq];
                wq = tanhf(sv.x + ard) * sv.y * dvd;
            }
            int m = min(16, p1 - chunk);
            for (int j = 0; j < m; j++) {
                int s   = __shfl_sync(gmask, sq, j, 16);
                float w = __shfl_sync(gmask, wq, j, 16);
                float4 hv = *(const float4*)&g_h[s * HID + q * 4];
                acc.x += w * hv.x; acc.y += w * hv.y;
                acc.z += w * hv.z; acc.w += w * hv.w;
            }
        }
        float2 svn = g_sv[node];
        float ws = tanhf(svn.x + ard) * dvd * dvd;
        int base = node * HID + q * 4;
        float4 hv  = *(const float4*)&g_h [base];
        float4 x0v = *(const float4*)&g_x0[base];
        float4 v;
        v.x = fmaxf(acc.x + ws * hv.x + EPS_RES * x0v.x, 0.f);
        v.y = fmaxf(acc.y + ws * hv.y + EPS_RES * x0v.y, 0.f);
        v.z = fmaxf(acc.z + ws * hv.z + EPS_RES * x0v.z, 0.f);
        v.w = fmaxf(acc.w + ws * hv.w + EPS_RES * x0v.w, 0.f);
        *(float4*)&g_out[base] = v;
        int c = q * 4;
        atomicAdd(&ssum[c + 0], v.x); atomicAdd(&ssum[c + 1], v.y);
        atomicAdd(&ssum[c + 2], v.z); atomicAdd(&ssum[c + 3], v.w);
        atomicAdd(&ssq[c + 0], v.x * v.x); atomicAdd(&ssq[c + 1], v.y * v.y);
        atomicAdd(&ssq[c + 2], v.z * v.z); atomicAdd(&ssq[c + 3], v.w * v.w);
    }
    __syncthreads();
    if (tid < HID) {
        atomicAdd(&g_stats[tid], ssum[tid]);
        atomicAdd(&g_stats[HID + tid], ssq[tid]);
    }
}

// ---------------- BN finalize ----------------
__global__ void k_finalize(const float* __restrict__ g, const float* __restrict__ b,
                           float inv_n) {
    int c = threadIdx.x;
    float mean = g_stats[c] * inv_n;
    float var = g_stats[HID + c] * inv_n - mean * mean;
    float sc = g[c] * rsqrtf(var + BN_EPS);
    g_scale[c] = sc;
    g_shift[c] = b[c] - mean * sc;
    g_stats[c] = 0.f;
    g_stats[HID + c] = 0.f;
}

// ---------------- head: t1 = bn3(y)[:bs] @ W1 + b1 ; stats (g_out -> g_h) ----------
__global__ void k_head1(const float* __restrict__ W1, const float* __restrict__ b1, int bs) {
    __shared__ float Ws[HID * HID];
    __shared__ float hs[4][HID];
    __shared__ float ssum[HID], ssq[HID];
    int tx = threadIdx.x, ty = threadIdx.y;
    int tid = ty * 64 + tx;
    for (int i = tid; i < HID * HID; i += 256) Ws[i] = W1[i];
    int row = blockIdx.x * 4 + ty;
    hs[ty][tx] = (row < bs) ? g_out[row * HID + tx] * g_scale[tx] + g_shift[tx] : 0.f;
    if (tid < HID) { ssum[tid] = 0.f; ssq[tid] = 0.f; }
    __syncthreads();
    float acc = b1[tx];
#pragma unroll
    for (int k = 0; k < HID; k++) acc += hs[ty][k] * Ws[k * HID + tx];
    if (row < bs) g_h[row * HID + tx] = acc; else acc = 0.f;
    atomicAdd(&ssum[tx], acc);
    atomicAdd(&ssq[tx], acc * acc);
    __syncthreads();
    if (tid < HID) {
        atomicAdd(&g_stats[tid], ssum[tid]);
        atomicAdd(&g_stats[HID + tid], ssq[tid]);
    }
}

// ---------------- head: t2 = relu(bn(t1)) @ W2 + b2 ; stats (g_h -> g_t2) ----------
__global__ void k_head2(const float* __restrict__ W2, const float* __restrict__ b2, int bs) {
    __shared__ float Ws[HID * 32];
    __shared__ float us[8][HID];
    __shared__ float ssum[32], ssq[32];
    int tx = threadIdx.x, ty = threadIdx.y;   // 32 x 8
    int tid = ty * 32 + tx;
    for (int i = tid; i < HID * 32; i += 256) Ws[i] = W2[i];
    int row = blockIdx.x * 8 + ty;
    if (row < bs) {
        float v0 = g_h[row * HID + tx]      * g_scale[tx]      + g_shift[tx];
        float v1 = g_h[row * HID + 32 + tx] * g_scale[32 + tx] + g_shift[32 + tx];
        us[ty][tx] = fmaxf(v0, 0.f);
        us[ty][32 + tx] = fmaxf(v1, 0.f);
    } else { us[ty][tx] = 0.f; us[ty][32 + tx] = 0.f; }
    if (tid < 32) { ssum[tid] = 0.f; ssq[tid] = 0.f; }
    __syncthreads();
    float acc = b2[tx];
#pragma unroll
    for (int k = 0; k < HID; k++) acc += us[ty][k] * Ws[k * 32 + tx];
    if (row < bs) g_t2[row * 32 + tx] = acc; else acc = 0.f;
    atomicAdd(&ssum[tx], acc);
    atomicAdd(&ssq[tx], acc * acc);
    __syncthreads();
    if (tid < 32) {
        atomicAdd(&g_stats[tid], ssum[tid]);
        atomicAdd(&g_stats[HID + tid], ssq[tid]);
    }
}

// ---------------- head: out = relu(bn(t2)) @ W3 + b3 ----------------
__global__ void k_head3(const float* __restrict__ W3, const float* __restrict__ b3,
                        float* __restrict__ out, int bs) {
    int gt = blockIdx.x * blockDim.x + threadIdx.x;
    int row = gt >> 5, lane = threadIdx.x & 31;
    if (row >= bs) return;
    float v = g_t2[row * 32 + lane] * g_scale[lane] + g_shift[lane];
    v = fmaxf(v, 0.f) * W3[lane];
#pragma unroll
    for (int o = 16; o; o >>= 1) v += __shfl_xor_sync(0xffffffffu, v, o);
    if (lane == 0) out[row] = v + b3[0];
}

extern "C" void kernel_launch(void* const* d_in, const int* in_sizes, int n_in,
                              void* d_out, int out_size) {
    const float* x    = (const float*)d_in[0];
    const int*   ei   = (const int*)d_in[1];
    int E = in_sizes[1] / 2;
    int n = in_sizes[0] / INCH;
    const float* W_in  = (const float*)d_in[3];
    const float* b_in  = (const float*)d_in[4];
    const float* att_l = (const float*)d_in[5];
    const float* att_r = (const float*)d_in[6];
    const float* bn_g  = (const float*)d_in[7];
    const float* bn_b  = (const float*)d_in[8];
    const float* W1  = (const float*)d_in[9];
    const float* b1  = (const float*)d_in[10];
    const float* g1  = (const float*)d_in[11];
    const float* be1 = (const float*)d_in[12];
    const float* W2  = (const float*)d_in[13];
    const float* b2  = (const float*)d_in[14];
    const float* g2  = (const float*)d_in[15];
    const float* be2 = (const float*)d_in[16];
    const float* W3  = (const float*)d_in[17];
    const float* b3  = (const float*)d_in[18];
    const int* src = ei;
    const int* dst = ei + E;
    int bs = out_size;   // output shape is (batch_size,)

    // One-time creation of side stream + fork/join events (first call is the
    // uncaptured correctness run; handles are plain infra, no device memory).
    static cudaStream_t s1 = nullptr;
    static cudaEvent_t ev_fork = nullptr, ev_join = nullptr;
    if (s1 == nullptr) {
        cudaStreamCreateWithFlags(&s1, cudaStreamNonBlocking);
        cudaEventCreateWithFlags(&ev_fork, cudaEventDisableTiming);
        cudaEventCreateWithFlags(&ev_join, cudaEventDisableTiming);
    }

    // Fork: CSR build on s1, input GEMM on the main (captured) stream.
    cudaEventRecord(ev_fork, 0);
    cudaStreamWaitEvent(s1, ev_fork, 0);

    k_init   <<<(n + 255) / 256, 256, 0, s1>>>(n);
    k_deg    <<<(E + 255) / 256, 256, 0, s1>>>(dst, E);
    k_off    <<<(n + 255) / 256, 256, 0, s1>>>(n);
    k_scatter<<<(E + 255) / 256, 256, 0, s1>>>(src, dst, E);
    cudaEventRecord(ev_join, s1);

    k_ingemm<<<(n + 63) / 64, 256>>>(x, W_in, b_in, n);

    // Join: everything after needs both CSR (+init'd scale/shift/stats) and x0.
    cudaStreamWaitEvent(0, ev_join, 0);

    for (int l = 0; l < 3; l++) {
        k_node_pre<<<(n * 16 + 255) / 256, 256>>>(att_l + l * HID, att_r + l * HID, n);
        k_agg<<<(n + 15) / 16, 256>>>(n);
        k_finalize<<<1, HID>>>(bn_g + l * HID, bn_b + l * HID, 1.0f / n);
    }

    k_head1<<<(bs + 3) / 4, dim3(64, 4)>>>(W1, b1, bs);
    k_finalize<<<1, HID>>>(g1, be1, 1.0f / bs);
    k_head2<<<(bs + 7) / 8, dim3(32, 8)>>>(W2, b2, bs);
    k_finalize<<<1, 32>>>(g2, be2, 1.0f / bs);
    k_head3<<<(bs * 32 + 255) / 256, 256>>>(W3, b3, (float*)d_out, bs);
}

// round 10
// speedup vs baseline: 1.6963x; 1.0170x over previous
#include <cuda_runtime.h>
#include <cuda_fp16.h>

#define HID 64
#define INCH 128
#define NMAX 50000
#define EMAX 1200000
#define EPS_RES 0.1f
#define BN_EPS 1e-5f

// ---------------- scratch (device globals; no allocation) ----------------
__device__ __align__(128) float  g_x0 [NMAX * HID];
__device__ __align__(128) float  g_b0 [NMAX * HID];   // fp32 ping
__device__ __align__(128) float  g_b1 [NMAX * HID];   // fp32 pong
__device__ __align__(128) __half g_hh0[NMAX * HID];   // fp16 ping (gather copy)
__device__ __align__(128) __half g_hh1[NMAX * HID];   // fp16 pong
__device__ __align__(128) float  g_t2 [NMAX * 32];
__device__ __align__(8) float2 g_sv[NMAX];   // (al[node], dinv[node])
__device__ float g_ar[NMAX];
__device__ float g_dinv[NMAX];
__device__ int   g_deg[NMAX];
__device__ int   g_off[NMAX];
__device__ int   g_cur[NMAX];
__device__ int   g_ctr;
__device__ int   g_csrc[EMAX];
// BN stat slots: 0..2 = layers, 3 = head1, 4 = head2. [slot][0:64]=sum, [64:128]=sumsq
__device__ float g_stats2[5 * 128];

struct h4 { __half2 a, b; };

// scalar BN param for one column from a stats slot (slot<0 -> identity)
__device__ __forceinline__ float2 bn1(int slot, const float* gam, const float* bet,
                                      float invn, int c) {
    if (slot < 0) return make_float2(1.f, 0.f);
    float m   = g_stats2[slot * 128 + c] * invn;
    float var = g_stats2[slot * 128 + HID + c] * invn - m * m;
    float s   = gam[c] * rsqrtf(var + BN_EPS);
    return make_float2(s, bet[c] - m * s);
}

// ---------------- init ----------------
__global__ void k_init(int n) {
    int i = blockIdx.x * blockDim.x + threadIdx.x;
    if (i < n) { g_deg[i] = 1; g_cur[i] = 0; }      // self-loop counted in deg
    if (i < 5 * 128) g_stats2[i] = 0.f;
    if (i == 0) g_ctr = 0;
}

__global__ void k_deg(const int* __restrict__ dst, int E) {
    int e = blockIdx.x * blockDim.x + threadIdx.x;
    if (e < E) atomicAdd(&g_deg[dst[e]], 1);
}

// ---------------- CSR range allocation: warp-aggregated atomic, + dinv ------------
__global__ void k_off(int n) {
    int i = blockIdx.x * blockDim.x + threadIdx.x;
    int lane = threadIdx.x & 31;
    int deg = (i < n) ? g_deg[i] : 1;
    if (i < n) g_dinv[i] = rsqrtf((float)deg);
    int v = deg - 1;            // in-edges excluding self-loop
    int pre = v;
#pragma unroll
    for (int o = 1; o < 32; o <<= 1) {
        int t = __shfl_up_sync(0xffffffffu, pre, o);
        if (lane >= o) pre += t;
    }
    int base = 0;
    if (lane == 31) base = atomicAdd(&g_ctr, pre);
    base = __shfl_sync(0xffffffffu, base, 31);
    if (i < n) g_off[i] = base + pre - v;
}

// ---------------- scatter edges into CSR (grouped by dst), src only --------------
__global__ void k_scatter(const int* __restrict__ src, const int* __restrict__ dst, int E) {
    int e = blockIdx.x * blockDim.x + threadIdx.x;
    if (e >= E) return;
    int d = dst[e];
    int pos = g_off[d] + atomicAdd(&g_cur[d], 1);
    g_csrc[pos] = src[e];
}

// ---------------- x0 = relu(x @ W_in + b_in); seed b0 (fp32) + hh0 (fp16) ---------
__global__ __launch_bounds__(256) void k_ingemm(
        const float* __restrict__ x, const float* __restrict__ W,
        const float* __restrict__ b, int n) {
    __shared__ float Ws[INCH * HID];
    __shared__ float xs[64][INCH];
    int tid = threadIdx.x;
    int tx = tid & 15;
    int ty = tid >> 4;
    int row0 = blockIdx.x * 64;

    const float4* W4 = (const float4*)W;
    float4* Ws4 = (float4*)Ws;
    for (int i = tid; i < INCH * HID / 4; i += 256) Ws4[i] = W4[i];
    for (int i = tid; i < 64 * 32; i += 256) {
        int r = i >> 5, c4 = (i & 31) * 4;
        int gr = row0 + r;
        float4 v = (gr < n) ? *(const float4*)&x[gr * INCH + c4]
                            : make_float4(0.f, 0.f, 0.f, 0.f);
        *(float4*)&xs[r][c4] = v;
    }
    __syncthreads();

    float acc[4][4];
#pragma unroll
    for (int i = 0; i < 4; i++)
#pragma unroll
        for (int j = 0; j < 4; j++) acc[i][j] = 0.f;

    int r0 = ty * 4, c0 = tx * 4;
#pragma unroll 4
    for (int k = 0; k < INCH; k++) {
        float4 wv = *(const float4*)&Ws[k * HID + c0];
        float a0 = xs[r0 + 0][k];
        float a1 = xs[r0 + 1][k];
        float a2 = xs[r0 + 2][k];
        float a3 = xs[r0 + 3][k];
        acc[0][0] += a0 * wv.x; acc[0][1] += a0 * wv.y; acc[0][2] += a0 * wv.z; acc[0][3] += a0 * wv.w;
        acc[1][0] += a1 * wv.x; acc[1][1] += a1 * wv.y; acc[1][2] += a1 * wv.z; acc[1][3] += a1 * wv.w;
        acc[2][0] += a2 * wv.x; acc[2][1] += a2 * wv.y; acc[2][2] += a2 * wv.z; acc[2][3] += a2 * wv.w;
        acc[3][0] += a3 * wv.x; acc[3][1] += a3 * wv.y; acc[3][2] += a3 * wv.z; acc[3][3] += a3 * wv.w;
    }

    float4 bv = *(const float4*)&b[c0];
#pragma unroll
    for (int i = 0; i < 4; i++) {
        int gr = row0 + r0 + i;
        if (gr >= n) break;
        float4 v;
        v.x = fmaxf(acc[i][0] + bv.x, 0.f);
        v.y = fmaxf(acc[i][1] + bv.y, 0.f);
        v.z = fmaxf(acc[i][2] + bv.z, 0.f);
        v.w = fmaxf(acc[i][3] + bv.w, 0.f);
        int base = gr * HID + c0;
        *(float4*)&g_x0[base] = v;
        *(float4*)&g_b0[base] = v;
        h4 hv;
        hv.a = __floats2half2_rn(v.x, v.y);
        hv.b = __floats2half2_rn(v.z, v.w);
        *(h4*)&g_hh0[base] = hv;
    }
}

// ---------------- per-node pre-pass: al/ar projections only (no h write) ----------
__global__ void k_node_pre(const float* __restrict__ attl,
                           const float* __restrict__ attr,
                           int slot, const float* __restrict__ gam,
                           const float* __restrict__ bet, float invn,
                           int inb, int n) {
    const float* bin = inb ? g_b1 : g_b0;
    int gt = blockIdx.x * blockDim.x + threadIdx.x;
    int node = gt >> 4, q = threadIdx.x & 15;
    unsigned gmask = 0xFFFFu << (threadIdx.x & 16);
    if (node >= n) return;
    int c0 = q * 4;
    int base = node * HID + c0;
    float4 y = *(const float4*)&bin[base];
    float2 p0 = bn1(slot, gam, bet, invn, c0 + 0);
    float2 p1 = bn1(slot, gam, bet, invn, c0 + 1);
    float2 p2 = bn1(slot, gam, bet, invn, c0 + 2);
    float2 p3 = bn1(slot, gam, bet, invn, c0 + 3);
    float4 h;
    h.x = y.x * p0.x + p0.y;
    h.y = y.y * p1.x + p1.y;
    h.z = y.z * p2.x + p2.y;
    h.w = y.w * p3.x + p3.y;
    float4 al4 = *(const float4*)&attl[c0];
    float4 ar4 = *(const float4*)&attr[c0];
    float a = h.x * al4.x + h.y * al4.y + h.z * al4.z + h.w * al4.w;
    float r = h.x * ar4.x + h.y * ar4.y + h.z * ar4.z + h.w * ar4.w;
#pragma unroll
    for (int o = 8; o; o >>= 1) {
        a += __shfl_xor_sync(gmask, a, o, 16);
        r += __shfl_xor_sync(gmask, r, o, 16);
    }
    if (q == 0) {
        g_ar[node] = r;
        g_sv[node] = make_float2(a, g_dinv[node]);
    }
}

// ---------------- aggregation: 16 threads/node, fp16 gather, BN hoisted -----------
// acc = sum w*out_raw[s] (fp16 gather); result = sc*acc + sh*wsum + EPS*x0; relu.
__global__ __launch_bounds__(256) void k_agg(
        int slot_in, const float* __restrict__ gam, const float* __restrict__ bet,
        float invn, int slot_out, int inb, int n) {
    const float*  bin  = inb ? g_b1  : g_b0;
    float*        bout = inb ? g_b0  : g_b1;
    const __half* hin  = inb ? g_hh1 : g_hh0;
    __half*       hout = inb ? g_hh0 : g_hh1;
    __shared__ float ssum[HID], ssq[HID];
    int tid = threadIdx.x;
    if (tid < HID) { ssum[tid] = 0.f; ssq[tid] = 0.f; }
    __syncthreads();
    int node = blockIdx.x * 16 + (tid >> 4);
    int q = tid & 15;
    unsigned gmask = 0xFFFFu << (tid & 16);   // this 16-group's lanes
    if (node < n) {
        float4 acc = make_float4(0.f, 0.f, 0.f, 0.f);
        float wsum = 0.f;
        int p0 = g_off[node];
        int p1 = p0 + g_deg[node] - 1;
        float dvd = g_dinv[node];
        float ard = g_ar[node];
        for (int chunk = p0; chunk < p1; chunk += 16) {
            int p = chunk + q;
            float wq = 0.f; int sq = 0;
            if (p < p1) {
                sq = __ldg(&g_csrc[p]);
                float2 sv = *(const float2*)&g_sv[sq];
                wq = tanhf(sv.x + ard) * sv.y * dvd;
            }
            int m = min(16, p1 - chunk);
            for (int j = 0; j < m; j++) {
                int s   = __shfl_sync(gmask, sq, j, 16);
                float w = __shfl_sync(gmask, wq, j, 16);
                h4 hraw = *(const h4*)&hin[s * HID + q * 4];
                float2 fa = __half22float2(hraw.a);
                float2 fb = __half22float2(hraw.b);
                acc.x += w * fa.x; acc.y += w * fa.y;
                acc.z += w * fb.x; acc.w += w * fb.y;
                wsum += w;
            }
        }
        // self-loop (fp32 row)
        float2 svn = g_sv[node];
        float ws = tanhf(svn.x + ard) * dvd * dvd;
        int base = node * HID + q * 4;
        float4 pv = *(const float4*)&bin[base];
        acc.x += ws * pv.x; acc.y += ws * pv.y;
        acc.z += ws * pv.z; acc.w += ws * pv.w;
        wsum += ws;
        // hoisted BN of h + residual + relu
        int c = q * 4;
        float2 b0 = bn1(slot_in, gam, bet, invn, c + 0);
        float2 b1 = bn1(slot_in, gam, bet, invn, c + 1);
        float2 b2 = bn1(slot_in, gam, bet, invn, c + 2);
        float2 b3 = bn1(slot_in, gam, bet, invn, c + 3);
        float4 x0v = *(const float4*)&g_x0[base];
        float4 v;
        v.x = fmaxf(b0.x * acc.x + b0.y * wsum + EPS_RES * x0v.x, 0.f);
        v.y = fmaxf(b1.x * acc.y + b1.y * wsum + EPS_RES * x0v.y, 0.f);
        v.z = fmaxf(b2.x * acc.z + b2.y * wsum + EPS_RES * x0v.z, 0.f);
        v.w = fmaxf(b3.x * acc.w + b3.y * wsum + EPS_RES * x0v.w, 0.f);
        *(float4*)&bout[base] = v;
        h4 hv;
        hv.a = __floats2half2_rn(v.x, v.y);
        hv.b = __floats2half2_rn(v.z, v.w);
        *(h4*)&hout[base] = hv;
        atomicAdd(&ssum[c + 0], v.x); atomicAdd(&ssum[c + 1], v.y);
        atomicAdd(&ssum[c + 2], v.z); atomicAdd(&ssum[c + 3], v.w);
        atomicAdd(&ssq[c + 0], v.x * v.x); atomicAdd(&ssq[c + 1], v.y * v.y);
        atomicAdd(&ssq[c + 2], v.z * v.z); atomicAdd(&ssq[c + 3], v.w * v.w);
    }
    __syncthreads();
    if (tid < HID) {
        atomicAdd(&g_stats2[slot_out * 128 + tid], ssum[tid]);
        atomicAdd(&g_stats2[slot_out * 128 + HID + tid], ssq[tid]);
    }
}

// ---------------- head: t1 = bn(y)[:bs] @ W1 + b1 ; stats (g_b1 -> g_b0) ----------
__global__ void k_head1(const float* __restrict__ W1, const float* __restrict__ b1,
                        int slot, const float* __restrict__ gam,
                        const float* __restrict__ bet, float invn, int bs) {
    __shared__ float Ws[HID * HID];
    __shared__ float hs[4][HID];
    __shared__ float ssum[HID], ssq[HID];
    int tx = threadIdx.x, ty = threadIdx.y;
    int tid = ty * 64 + tx;
    for (int i = tid; i < HID * HID; i += 256) Ws[i] = W1[i];
    int row = blockIdx.x * 4 + ty;
    float2 p = bn1(slot, gam, bet, invn, tx);
    hs[ty][tx] = (row < bs) ? g_b1[row * HID + tx] * p.x + p.y : 0.f;
    if (tid < HID) { ssum[tid] = 0.f; ssq[tid] = 0.f; }
    __syncthreads();
    float acc = b1[tx];
#pragma unroll
    for (int k = 0; k < HID; k++) acc += hs[ty][k] * Ws[k * HID + tx];
    if (row < bs) g_b0[row * HID + tx] = acc; else acc = 0.f;
    atomicAdd(&ssum[tx], acc);
    atomicAdd(&ssq[tx], acc * acc);
    __syncthreads();
    if (tid < HID) {
        atomicAdd(&g_stats2[3 * 128 + tid], ssum[tid]);
        atomicAdd(&g_stats2[3 * 128 + HID + tid], ssq[tid]);
    }
}

// ---------------- head: t2 = relu(bn(t1)) @ W2 + b2 ; stats (g_b0 -> g_t2) --------
__global__ void k_head2(const float* __restrict__ W2, const float* __restrict__ b2,
                        int slot, const float* __restrict__ gam,
                        const float* __restrict__ bet, float invn, int bs) {
    __shared__ float Ws[HID * 32];
    __shared__ float us[8][HID];
    __shared__ float ssum[32], ssq[32];
    int tx = threadIdx.x, ty = threadIdx.y;   // 32 x 8
    int tid = ty * 32 + tx;
    for (int i = tid; i < HID * 32; i += 256) Ws[i] = W2[i];
    int row = blockIdx.x * 8 + ty;
    float2 pa = bn1(slot, gam, bet, invn, tx);
    float2 pb = bn1(slot, gam, bet, invn, 32 + tx);
    if (row < bs) {
        float v0 = g_b0[row * HID + tx]      * pa.x + pa.y;
        float v1 = g_b0[row * HID + 32 + tx] * pb.x + pb.y;
        us[ty][tx] = fmaxf(v0, 0.f);
        us[ty][32 + tx] = fmaxf(v1, 0.f);
    } else { us[ty][tx] = 0.f; us[ty][32 + tx] = 0.f; }
    if (tid < 32) { ssum[tid] = 0.f; ssq[tid] = 0.f; }
    __syncthreads();
    float acc = b2[tx];
#pragma unroll
    for (int k = 0; k < HID; k++) acc += us[ty][k] * Ws[k * 32 + tx];
    if (row < bs) g_t2[row * 32 + tx] = acc; else acc = 0.f;
    atomicAdd(&ssum[tx], acc);
    atomicAdd(&ssq[tx], acc * acc);
    __syncthreads();
    if (tid < 32) {
        atomicAdd(&g_stats2[4 * 128 + tid], ssum[tid]);
        atomicAdd(&g_stats2[4 * 128 + HID + tid], ssq[tid]);
    }
}

// ---------------- head: out = relu(bn(t2)) @ W3 + b3 ----------------
__global__ void k_head3(const float* __restrict__ W3, const float* __restrict__ b3,
                        int slot, const float* __restrict__ gam,
                        const float* __restrict__ bet, float invn,
                        float* __restrict__ out, int bs) {
    int gt = blockIdx.x * blockDim.x + threadIdx.x;
    int row = gt >> 5, lane = threadIdx.x & 31;
    if (row >= bs) return;
    float2 p = bn1(slot, gam, bet, invn, lane);
    float v = g_t2[row * 32 + lane] * p.x + p.y;
    v = fmaxf(v, 0.f) * W3[lane];
#pragma unroll
    for (int o = 16; o; o >>= 1) v += __shfl_xor_sync(0xffffffffu, v, o);
    if (lane == 0) out[row] = v + b3[0];
}

extern "C" void kernel_launch(void* const* d_in, const int* in_sizes, int n_in,
                              void* d_out, int out_size) {
    const float* x    = (const float*)d_in[0];
    const int*   ei   = (const int*)d_in[1];
    int E = in_sizes[1] / 2;
    int n = in_sizes[0] / INCH;
    const float* W_in  = (const float*)d_in[3];
    const float* b_in  = (const float*)d_in[4];
    const float* att_l = (const float*)d_in[5];
    const float* att_r = (const float*)d_in[6];
    const float* bn_g  = (const float*)d_in[7];
    const float* bn_b  = (const float*)d_in[8];
    const float* W1  = (const float*)d_in[9];
    const float* b1  = (const float*)d_in[10];
    const float* g1  = (const float*)d_in[11];
    const float* be1 = (const float*)d_in[12];
    const float* W2  = (const float*)d_in[13];
    const float* b2  = (const float*)d_in[14];
    const float* g2  = (const float*)d_in[15];
    const float* be2 = (const float*)d_in[16];
    const float* W3  = (const float*)d_in[17];
    const float* b3  = (const float*)d_in[18];
    const int* src = ei;
    const int* dst = ei + E;
    int bs = out_size;
    float invn = 1.0f / n, invbs = 1.0f / bs;

    static cudaStream_t s1 = nullptr;
    static cudaEvent_t ev_fork = nullptr, ev_join = nullptr;
    if (s1 == nullptr) {
        cudaStreamCreateWithFlags(&s1, cudaStreamNonBlocking);
        cudaEventCreateWithFlags(&ev_fork, cudaEventDisableTiming);
        cudaEventCreateWithFlags(&ev_join, cudaEventDisableTiming);
    }

    // Fork: CSR build on s1, input GEMM on the main (captured) stream.
    cudaEventRecord(ev_fork, 0);
    cudaStreamWaitEvent(s1, ev_fork, 0);

    k_init   <<<(n + 255) / 256, 256, 0, s1>>>(n);
    k_deg    <<<(E + 255) / 256, 256, 0, s1>>>(dst, E);
    k_off    <<<(n + 255) / 256, 256, 0, s1>>>(n);
    k_scatter<<<(E + 255) / 256, 256, 0, s1>>>(src, dst, E);
    cudaEventRecord(ev_join, s1);

    k_ingemm<<<(n + 63) / 64, 256>>>(x, W_in, b_in, n);

    cudaStreamWaitEvent(0, ev_join, 0);

    for (int l = 0; l < 3; l++) {
        int slot_in = l - 1;               // -1 = identity BN (layer 0)
        const float* gam = bn_g + (l > 0 ? (l - 1) * HID : 0);
        const float* bet = bn_b + (l > 0 ? (l - 1) * HID : 0);
        int inb = l & 1;
        k_node_pre<<<(n * 16 + 255) / 256, 256>>>(
            att_l + l * HID, att_r + l * HID, slot_in, gam, bet, invn, inb, n);
        k_agg<<<(n + 15) / 16, 256>>>(slot_in, gam, bet, invn, l, inb, n);
    }

    // final buffer is g_b1 (agg2: in=0 -> out=1)
    k_head1<<<(bs + 3) / 4, dim3(64, 4)>>>(W1, b1, 2, bn_g + 2 * HID, bn_b + 2 * HID, invn, bs);
    k_head2<<<(bs + 7) / 8, dim3(32, 8)>>>(W2, b2, 3, g1, be1, invbs, bs);
    k_head3<<<(bs * 32 + 255) / 256, 256>>>(W3, b3, 4, g2, be2, invbs, (float*)d_out, bs);
}

// round 11
// speedup vs baseline: 1.7222x; 1.0153x over previous
#include <cuda_runtime.h>

#define HID 64
#define INCH 128
#define NMAX 50000
#define EMAX 1200000
#define EPS_RES 0.1f
#define BN_EPS 1e-5f

// ---------------- scratch (device globals; no allocation) ----------------
__device__ __align__(128) float  g_x0 [NMAX * HID];
__device__ __align__(128) float  g_b0 [NMAX * HID];   // fp32 ping
__device__ __align__(128) float  g_b1 [NMAX * HID];   // fp32 pong
__device__ __align__(128) float  g_t2 [NMAX * 32];
__device__ __align__(8) float2 g_sv[NMAX];   // (al[node], dinv[node])
__device__ float g_ar[NMAX];
__device__ float g_dinv[NMAX];
__device__ int   g_deg[NMAX];
__device__ int   g_off[NMAX];
__device__ int   g_cur[NMAX];
__device__ int   g_ctr;
__device__ int   g_csrc[EMAX];
// BN stat slots: 0..2 = layers, 3 = head1, 4 = head2. [slot][0:64]=sum, [64:128]=sumsq
__device__ float g_stats2[5 * 128];

// scalar BN param for one column from a stats slot (slot<0 -> identity)
__device__ __forceinline__ float2 bn1(int slot, const float* gam, const float* bet,
                                      float invn, int c) {
    if (slot < 0) return make_float2(1.f, 0.f);
    float m   = g_stats2[slot * 128 + c] * invn;
    float var = g_stats2[slot * 128 + HID + c] * invn - m * m;
    float s   = gam[c] * rsqrtf(var + BN_EPS);
    return make_float2(s, bet[c] - m * s);
}

// ---------------- init ----------------
__global__ void k_init(int n) {
    int i = blockIdx.x * blockDim.x + threadIdx.x;
    if (i < n) { g_deg[i] = 1; g_cur[i] = 0; }      // self-loop counted in deg
    if (i < 5 * 128) g_stats2[i] = 0.f;
    if (i == 0) g_ctr = 0;
}

__global__ void k_deg(const int* __restrict__ dst, int E) {
    int e = blockIdx.x * blockDim.x + threadIdx.x;
    if (e < E) atomicAdd(&g_deg[dst[e]], 1);
}

// ---------------- CSR range allocation: warp-aggregated atomic, + dinv ------------
__global__ void k_off(int n) {
    int i = blockIdx.x * blockDim.x + threadIdx.x;
    int lane = threadIdx.x & 31;
    int deg = (i < n) ? g_deg[i] : 1;
    if (i < n) g_dinv[i] = rsqrtf((float)deg);
    int v = deg - 1;            // in-edges excluding self-loop
    int pre = v;
#pragma unroll
    for (int o = 1; o < 32; o <<= 1) {
        int t = __shfl_up_sync(0xffffffffu, pre, o);
        if (lane >= o) pre += t;
    }
    int base = 0;
    if (lane == 31) base = atomicAdd(&g_ctr, pre);
    base = __shfl_sync(0xffffffffu, base, 31);
    if (i < n) g_off[i] = base + pre - v;
}

// ---------------- scatter edges into CSR (grouped by dst), src only --------------
__global__ void k_scatter(const int* __restrict__ src, const int* __restrict__ dst, int E) {
    int e = blockIdx.x * blockDim.x + threadIdx.x;
    if (e >= E) return;
    int d = dst[e];
    int pos = g_off[d] + atomicAdd(&g_cur[d], 1);
    g_csrc[pos] = src[e];
}

// ---------------- x0 = relu(x @ W_in + b_in); seed b0 ----------------
__global__ __launch_bounds__(256) void k_ingemm(
        const float* __restrict__ x, const float* __restrict__ W,
        const float* __restrict__ b, int n) {
    __shared__ float Ws[INCH * HID];
    __shared__ float xs[64][INCH];
    int tid = threadIdx.x;
    int tx = tid & 15;
    int ty = tid >> 4;
    int row0 = blockIdx.x * 64;

    const float4* W4 = (const float4*)W;
    float4* Ws4 = (float4*)Ws;
    for (int i = tid; i < INCH * HID / 4; i += 256) Ws4[i] = W4[i];
    for (int i = tid; i < 64 * 32; i += 256) {
        int r = i >> 5, c4 = (i & 31) * 4;
        int gr = row0 + r;
        float4 v = (gr < n) ? *(const float4*)&x[gr * INCH + c4]
                            : make_float4(0.f, 0.f, 0.f, 0.f);
        *(float4*)&xs[r][c4] = v;
    }
    __syncthreads();

    float acc[4][4];
#pragma unroll
    for (int i = 0; i < 4; i++)
#pragma unroll
        for (int j = 0; j < 4; j++) acc[i][j] = 0.f;

    int r0 = ty * 4, c0 = tx * 4;
#pragma unroll 4
    for (int k = 0; k < INCH; k++) {
        float4 wv = *(const float4*)&Ws[k * HID + c0];
        float a0 = xs[r0 + 0][k];
        float a1 = xs[r0 + 1][k];
        float a2 = xs[r0 + 2][k];
        float a3 = xs[r0 + 3][k];
        acc[0][0] += a0 * wv.x; acc[0][1] += a0 * wv.y; acc[0][2] += a0 * wv.z; acc[0][3] += a0 * wv.w;
        acc[1][0] += a1 * wv.x; acc[1][1] += a1 * wv.y; acc[1][2] += a1 * wv.z; acc[1][3] += a1 * wv.w;
        acc[2][0] += a2 * wv.x; acc[2][1] += a2 * wv.y; acc[2][2] += a2 * wv.z; acc[2][3] += a2 * wv.w;
        acc[3][0] += a3 * wv.x; acc[3][1] += a3 * wv.y; acc[3][2] += a3 * wv.z; acc[3][3] += a3 * wv.w;
    }

    float4 bv = *(const float4*)&b[c0];
#pragma unroll
    for (int i = 0; i < 4; i++) {
        int gr = row0 + r0 + i;
        if (gr >= n) break;
        float4 v;
        v.x = fmaxf(acc[i][0] + bv.x, 0.f);
        v.y = fmaxf(acc[i][1] + bv.y, 0.f);
        v.z = fmaxf(acc[i][2] + bv.z, 0.f);
        v.w = fmaxf(acc[i][3] + bv.w, 0.f);
        int base = gr * HID + c0;
        *(float4*)&g_x0[base] = v;
        *(float4*)&g_b0[base] = v;
    }
}

// ---------------- per-node pre-pass: al/ar projections only ----------------
__global__ void k_node_pre(const float* __restrict__ attl,
                           const float* __restrict__ attr,
                           int slot, const float* __restrict__ gam,
                           const float* __restrict__ bet, float invn,
                           int inb, int n) {
    const float* bin = inb ? g_b1 : g_b0;
    int gt = blockIdx.x * blockDim.x + threadIdx.x;
    int node = gt >> 4, q = threadIdx.x & 15;
    unsigned gmask = 0xFFFFu << (threadIdx.x & 16);
    if (node >= n) return;
    int c0 = q * 4;
    int base = node * HID + c0;
    float4 y = *(const float4*)&bin[base];
    float2 p0 = bn1(slot, gam, bet, invn, c0 + 0);
    float2 p1 = bn1(slot, gam, bet, invn, c0 + 1);
    float2 p2 = bn1(slot, gam, bet, invn, c0 + 2);
    float2 p3 = bn1(slot, gam, bet, invn, c0 + 3);
    float4 h;
    h.x = y.x * p0.x + p0.y;
    h.y = y.y * p1.x + p1.y;
    h.z = y.z * p2.x + p2.y;
    h.w = y.w * p3.x + p3.y;
    float4 al4 = *(const float4*)&attl[c0];
    float4 ar4 = *(const float4*)&attr[c0];
    float a = h.x * al4.x + h.y * al4.y + h.z * al4.z + h.w * al4.w;
    float r = h.x * ar4.x + h.y * ar4.y + h.z * ar4.z + h.w * ar4.w;
#pragma unroll
    for (int o = 8; o; o >>= 1) {
        a += __shfl_xor_sync(gmask, a, o, 16);
        r += __shfl_xor_sync(gmask, r, o, 16);
    }
    if (q == 0) {
        g_ar[node] = r;
        g_sv[node] = make_float2(a, g_dinv[node]);
    }
}

// ---------------- aggregation: 16 threads/node, BN hoisted, unrolled chunks -------
// Full 16-edge chunks use a compile-time inner loop (unroll 4 -> MLP 4);
// only the final partial chunk takes the variable-bound loop.
__global__ __launch_bounds__(256) void k_agg(
        int slot_in, const float* __restrict__ gam, const float* __restrict__ bet,
        float invn, int slot_out, int inb, int n) {
    const float* bin  = inb ? g_b1 : g_b0;
    float*       bout = inb ? g_b0 : g_b1;
    __shared__ float ssum[HID], ssq[HID];
    int tid = threadIdx.x;
    if (tid < HID) { ssum[tid] = 0.f; ssq[tid] = 0.f; }
    __syncthreads();
    int node = blockIdx.x * 16 + (tid >> 4);
    int q = tid & 15;
    unsigned gmask = 0xFFFFu << (tid & 16);   // this 16-group's lanes
    if (node < n) {
        float4 acc = make_float4(0.f, 0.f, 0.f, 0.f);
        float wsum = 0.f;
        int p0 = g_off[node];
        int p1 = p0 + g_deg[node] - 1;
        float dvd = g_dinv[node];
        float ard = g_ar[node];
        int chunk = p0;
        // full chunks: compile-time 16 iterations, unroll 4 for load ILP
        for (; chunk + 16 <= p1; chunk += 16) {
            int sq = __ldg(&g_csrc[chunk + q]);
            float2 sv = *(const float2*)&g_sv[sq];
            float wq = tanhf(sv.x + ard) * sv.y * dvd;
#pragma unroll 4
            for (int j = 0; j < 16; j++) {
                int s   = __shfl_sync(gmask, sq, j, 16);
                float w = __shfl_sync(gmask, wq, j, 16);
                float4 hv = *(const float4*)&bin[s * HID + q * 4];
                acc.x += w * hv.x; acc.y += w * hv.y;
                acc.z += w * hv.z; acc.w += w * hv.w;
                wsum += w;
            }
        }
        // partial tail chunk
        if (chunk < p1) {
            int p = chunk + q;
            float wq = 0.f; int sq = 0;
            if (p < p1) {
                sq = __ldg(&g_csrc[p]);
                float2 sv = *(const float2*)&g_sv[sq];
                wq = tanhf(sv.x + ard) * sv.y * dvd;
            }
            int m = p1 - chunk;
            for (int j = 0; j < m; j++) {
                int s   = __shfl_sync(gmask, sq, j, 16);
                float w = __shfl_sync(gmask, wq, j, 16);
                float4 hv = *(const float4*)&bin[s * HID + q * 4];
                acc.x += w * hv.x; acc.y += w * hv.y;
                acc.z += w * hv.z; acc.w += w * hv.w;
                wsum += w;
            }
        }
        // self-loop (fp32 row)
        float2 svn = g_sv[node];
        float ws = tanhf(svn.x + ard) * dvd * dvd;
        int base = node * HID + q * 4;
        float4 pv = *(const float4*)&bin[base];
        acc.x += ws * pv.x; acc.y += ws * pv.y;
        acc.z += ws * pv.z; acc.w += ws * pv.w;
        wsum += ws;
        // hoisted BN of h + residual + relu
        int c = q * 4;
        float2 b0 = bn1(slot_in, gam, bet, invn, c + 0);
        float2 b1 = bn1(slot_in, gam, bet, invn, c + 1);
        float2 b2 = bn1(slot_in, gam, bet, invn, c + 2);
        float2 b3 = bn1(slot_in, gam, bet, invn, c + 3);
        float4 x0v = *(const float4*)&g_x0[base];
        float4 v;
        v.x = fmaxf(b0.x * acc.x + b0.y * wsum + EPS_RES * x0v.x, 0.f);
        v.y = fmaxf(b1.x * acc.y + b1.y * wsum + EPS_RES * x0v.y, 0.f);
        v.z = fmaxf(b2.x * acc.z + b2.y * wsum + EPS_RES * x0v.z, 0.f);
        v.w = fmaxf(b3.x * acc.w + b3.y * wsum + EPS_RES * x0v.w, 0.f);
        *(float4*)&bout[base] = v;
        atomicAdd(&ssum[c + 0], v.x); atomicAdd(&ssum[c + 1], v.y);
        atomicAdd(&ssum[c + 2], v.z); atomicAdd(&ssum[c + 3], v.w);
        atomicAdd(&ssq[c + 0], v.x * v.x); atomicAdd(&ssq[c + 1], v.y * v.y);
        atomicAdd(&ssq[c + 2], v.z * v.z); atomicAdd(&ssq[c + 3], v.w * v.w);
    }
    __syncthreads();
    if (tid < HID) {
        atomicAdd(&g_stats2[slot_out * 128 + tid], ssum[tid]);
        atomicAdd(&g_stats2[slot_out * 128 + HID + tid], ssq[tid]);
    }
}

// ---------------- head: t1 = bn(y)[:bs] @ W1 + b1 ; stats (g_b1 -> g_b0) ----------
__global__ void k_head1(const float* __restrict__ W1, const float* __restrict__ b1,
                        int slot, const float* __restrict__ gam,
                        const float* __restrict__ bet, float invn, int bs) {
    __shared__ float Ws[HID * HID];
    __shared__ float hs[4][HID];
    __shared__ float ssum[HID], ssq[HID];
    int tx = threadIdx.x, ty = threadIdx.y;
    int tid = ty * 64 + tx;
    for (int i = tid; i < HID * HID; i += 256) Ws[i] = W1[i];
    int row = blockIdx.x * 4 + ty;
    float2 p = bn1(slot, gam, bet, invn, tx);
    hs[ty][tx] = (row < bs) ? g_b1[row * HID + tx] * p.x + p.y : 0.f;
    if (tid < HID) { ssum[tid] = 0.f; ssq[tid] = 0.f; }
    __syncthreads();
    float acc = b1[tx];
#pragma unroll
    for (int k = 0; k < HID; k++) acc += hs[ty][k] * Ws[k * HID + tx];
    if (row < bs) g_b0[row * HID + tx] = acc; else acc = 0.f;
    atomicAdd(&ssum[tx], acc);
    atomicAdd(&ssq[tx], acc * acc);
    __syncthreads();
    if (tid < HID) {
        atomicAdd(&g_stats2[3 * 128 + tid], ssum[tid]);
        atomicAdd(&g_stats2[3 * 128 + HID + tid], ssq[tid]);
    }
}

// ---------------- head: t2 = relu(bn(t1)) @ W2 + b2 ; stats (g_b0 -> g_t2) --------
__global__ void k_head2(const float* __restrict__ W2, const float* __restrict__ b2,
                        int slot, const float* __restrict__ gam,
                        const float* __restrict__ bet, float invn, int bs) {
    __shared__ float Ws[HID * 32];
    __shared__ float us[8][HID];
    __shared__ float ssum[32], ssq[32];
    int tx = threadIdx.x, ty = threadIdx.y;   // 32 x 8
    int tid = ty * 32 + tx;
    for (int i = tid; i < HID * 32; i += 256) Ws[i] = W2[i];
    int row = blockIdx.x * 8 + ty;
    float2 pa = bn1(slot, gam, bet, invn, tx);
    float2 pb = bn1(slot, gam, bet, invn, 32 + tx);
    if (row < bs) {
        float v0 = g_b0[row * HID + tx]      * pa.x + pa.y;
        float v1 = g_b0[row * HID + 32 + tx] * pb.x + pb.y;
        us[ty][tx] = fmaxf(v0, 0.f);
        us[ty][32 + tx] = fmaxf(v1, 0.f);
    } else { us[ty][tx] = 0.f; us[ty][32 + tx] = 0.f; }
    if (tid < 32) { ssum[tid] = 0.f; ssq[tid] = 0.f; }
    __syncthreads();
    float acc = b2[tx];
#pragma unroll
    for (int k = 0; k < HID; k++) acc += us[ty][k] * Ws[k * 32 + tx];
    if (row < bs) g_t2[row * 32 + tx] = acc; else acc = 0.f;
    atomicAdd(&ssum[tx], acc);
    atomicAdd(&ssq[tx], acc * acc);
    __syncthreads();
    if (tid < 32) {
        atomicAdd(&g_stats2[4 * 128 + tid], ssum[tid]);
        atomicAdd(&g_stats2[4 * 128 + HID + tid], ssq[tid]);
    }
}

// ---------------- head: out = relu(bn(t2)) @ W3 + b3 ----------------
__global__ void k_head3(const float* __restrict__ W3, const float* __restrict__ b3,
                        int slot, const float* __restrict__ gam,
                        const float* __restrict__ bet, float invn,
                        float* __restrict__ out, int bs) {
    int gt = blockIdx.x * blockDim.x + threadIdx.x;
    int row = gt >> 5, lane = threadIdx.x & 31;
    if (row >= bs) return;
    float2 p = bn1(slot, gam, bet, invn, lane);
    float v = g_t2[row * 32 + lane] * p.x + p.y;
    v = fmaxf(v, 0.f) * W3[lane];
#pragma unroll
    for (int o = 16; o; o >>= 1) v += __shfl_xor_sync(0xffffffffu, v, o);
    if (lane == 0) out[row] = v + b3[0];
}

extern "C" void kernel_launch(void* const* d_in, const int* in_sizes, int n_in,
                              void* d_out, int out_size) {
    const float* x    = (const float*)d_in[0];
    const int*   ei   = (const int*)d_in[1];
    int E = in_sizes[1] / 2;
    int n = in_sizes[0] / INCH;
    const float* W_in  = (const float*)d_in[3];
    const float* b_in  = (const float*)d_in[4];
    const float* att_l = (const float*)d_in[5];
    const float* att_r = (const float*)d_in[6];
    const float* bn_g  = (const float*)d_in[7];
    const float* bn_b  = (const float*)d_in[8];
    const float* W1  = (const float*)d_in[9];
    const float* b1  = (const float*)d_in[10];
    const float* g1  = (const float*)d_in[11];
    const float* be1 = (const float*)d_in[12];
    const float* W2  = (const float*)d_in[13];
    const float* b2  = (const float*)d_in[14];
    const float* g2  = (const float*)d_in[15];
    const float* be2 = (const float*)d_in[16];
    const float* W3  = (const float*)d_in[17];
    const float* b3  = (const float*)d_in[18];
    const int* src = ei;
    const int* dst = ei + E;
    int bs = out_size;
    float invn = 1.0f / n, invbs = 1.0f / bs;

    static cudaStream_t s1 = nullptr;
    static cudaEvent_t ev_fork = nullptr, ev_join = nullptr;
    if (s1 == nullptr) {
        cudaStreamCreateWithFlags(&s1, cudaStreamNonBlocking);
        cudaEventCreateWithFlags(&ev_fork, cudaEventDisableTiming);
        cudaEventCreateWithFlags(&ev_join, cudaEventDisableTiming);
    }

    // Fork: CSR build on s1, input GEMM on the main (captured) stream.
    cudaEventRecord(ev_fork, 0);
    cudaStreamWaitEvent(s1, ev_fork, 0);

    k_init   <<<(n + 255) / 256, 256, 0, s1>>>(n);
    k_deg    <<<(E + 255) / 256, 256, 0, s1>>>(dst, E);
    k_off    <<<(n + 255) / 256, 256, 0, s1>>>(n);
    k_scatter<<<(E + 255) / 256, 256, 0, s1>>>(src, dst, E);
    cudaEventRecord(ev_join, s1);

    k_ingemm<<<(n + 63) / 64, 256>>>(x, W_in, b_in, n);

    cudaStreamWaitEvent(0, ev_join, 0);

    for (int l = 0; l < 3; l++) {
        int slot_in = l - 1;               // -1 = identity BN (layer 0)
        const float* gam = bn_g + (l > 0 ? (l - 1) * HID : 0);
        const float* bet = bn_b + (l > 0 ? (l - 1) * HID : 0);
        int inb = l & 1;
        k_node_pre<<<(n * 16 + 255) / 256, 256>>>(
            att_l + l * HID, att_r + l * HID, slot_in, gam, bet, invn, inb, n);
        k_agg<<<(n + 15) / 16, 256>>>(slot_in, gam, bet, invn, l, inb, n);
    }

    // final buffer is g_b1 (agg2: in=0 -> out=1)
    k_head1<<<(bs + 3) / 4, dim3(64, 4)>>>(W1, b1, 2, bn_g + 2 * HID, bn_b + 2 * HID, invn, bs);
    k_head2<<<(bs + 7) / 8, dim3(32, 8)>>>(W2, b2, 3, g1, be1, invbs, bs);
    k_head3<<<(bs * 32 + 255) / 256, 256>>>(W3, b3, 4, g2, be2, invbs, (float*)d_out, bs);
}